// round 1
// baseline (speedup 1.0000x reference)
#include <cuda_runtime.h>
#include <cuda_bf16.h>
#include <math.h>

// Problem constants
#define BB 4
#define SS 1024
#define DD 1024
#define HH 16
#define DH 64
#define GM_M (BB*SS)   // 4096
#define GM_N DD        // 1024
#define GM_K DD        // 1024
#define QROWS 32

// Device scratch for projected Q, K, V (row-major [B*S, D])
__device__ float g_Q[GM_M * GM_N];
__device__ float g_K[GM_M * GM_N];
__device__ float g_V[GM_M * GM_N];

// ---------------------------------------------------------------------------
// Kernel 1: fused QKV projection. grid.z selects which of the three GEMMs.
// C[M,N] = X[M,K] @ W[K,N] + bias.  BM=BN=64, BK=16, 256 threads, 4x4/thread.
// ---------------------------------------------------------------------------
__global__ __launch_bounds__(256) void qkv_proj_kernel(
    const float* __restrict__ Xq, const float* __restrict__ Xk, const float* __restrict__ Xv,
    const float* __restrict__ Wq, const float* __restrict__ Wk, const float* __restrict__ Wv,
    const float* __restrict__ bq, const float* __restrict__ bk, const float* __restrict__ bv)
{
    const float* X; const float* W; const float* bias; float* Out;
    int z = blockIdx.z;
    if (z == 0)      { X = Xq; W = Wq; bias = bq; Out = g_Q; }
    else if (z == 1) { X = Xk; W = Wk; bias = bk; Out = g_K; }
    else             { X = Xv; W = Wv; bias = bv; Out = g_V; }

    __shared__ float As[16][68];   // A tile stored transposed [k][m], padded
    __shared__ float Bs[16][64];   // B tile [k][n]

    const int tid = threadIdx.x;
    const int tx  = tid & 15;      // 0..15 -> n
    const int ty  = tid >> 4;      // 0..15 -> m
    const int row0 = blockIdx.y * 64;
    const int col0 = blockIdx.x * 64;

    // global load indices (one float4 per thread per tile for A and B)
    const int a_row = tid >> 2;          // 0..63
    const int a_col = (tid & 3) * 4;     // 0,4,8,12
    const int b_row = tid >> 4;          // 0..15
    const int b_col = (tid & 15) * 4;    // 0..60

    const float* Aptr = X + (size_t)(row0 + a_row) * GM_K + a_col;
    const float* Bptr = W + (size_t)b_row * GM_N + col0 + b_col;

    float acc[4][4];
    #pragma unroll
    for (int i = 0; i < 4; ++i)
        #pragma unroll
        for (int j = 0; j < 4; ++j) acc[i][j] = 0.0f;

    for (int t = 0; t < GM_K / 16; ++t) {
        float4 a4 = *(const float4*)Aptr;
        float4 b4 = *(const float4*)Bptr;
        __syncthreads();
        As[a_col + 0][a_row] = a4.x;
        As[a_col + 1][a_row] = a4.y;
        As[a_col + 2][a_row] = a4.z;
        As[a_col + 3][a_row] = a4.w;
        *(float4*)&Bs[b_row][b_col] = b4;
        __syncthreads();

        #pragma unroll
        for (int kk = 0; kk < 16; ++kk) {
            float4 av4 = *(const float4*)&As[kk][ty * 4];
            float4 bv4 = *(const float4*)&Bs[kk][tx * 4];
            float av[4] = {av4.x, av4.y, av4.z, av4.w};
            float bv[4] = {bv4.x, bv4.y, bv4.z, bv4.w};
            #pragma unroll
            for (int i = 0; i < 4; ++i)
                #pragma unroll
                for (int j = 0; j < 4; ++j)
                    acc[i][j] = fmaf(av[i], bv[j], acc[i][j]);
        }
        Aptr += 16;
        Bptr += (size_t)16 * GM_N;
    }

    #pragma unroll
    for (int i = 0; i < 4; ++i) {
        int r = row0 + ty * 4 + i;
        #pragma unroll
        for (int j = 0; j < 4; ++j) {
            int c = col0 + tx * 4 + j;
            Out[(size_t)r * GM_N + c] = acc[i][j] + bias[c];
        }
    }
}

// ---------------------------------------------------------------------------
// Kernel 2: attention. One CTA handles 32 query rows of one (batch, head).
// Score tile [32 x 1024] lives in shared memory. Softmax in-place, attn
// written once to global; 1/sum folded into the context epilogue.
// ---------------------------------------------------------------------------
__global__ __launch_bounds__(256) void attn_kernel(
    float* __restrict__ ctx, float* __restrict__ attn)
{
    extern __shared__ float sm[];
    float* Ssc  = sm;                          // 32*1024
    float* Qt   = Ssc + QROWS * SS;            // 64*33 (Q transposed [d][i])
    float* KVs  = Qt + DH * 33;                // 128*65 (K or V tile)
    float* invs = KVs + 128 * 65;              // 32 per-row 1/sum

    const int q0 = blockIdx.x * QROWS;
    const int h  = blockIdx.y;
    const int b  = blockIdx.z;
    const int tid = threadIdx.x;
    const int tx = tid & 31;     // 0..31
    const int ty = tid >> 5;     // 0..7

    const float* Qg = g_Q + (size_t)b * SS * DD + h * DH;
    const float* Kg = g_K + (size_t)b * SS * DD + h * DH;
    const float* Vg = g_V + (size_t)b * SS * DD + h * DH;

    // Load Q tile transposed: Qt[d][i]
    for (int idx = tid; idx < QROWS * DH; idx += 256) {
        int d = idx & 63;
        int i = idx >> 6;
        Qt[d * 33 + i] = Qg[(size_t)(q0 + i) * DD + d];
    }

    // ---- scores: S[i][j] = 0.125 * sum_d Q[i][d]*K[j][d] ----
    for (int jt = 0; jt < SS / 128; ++jt) {
        const int j0 = jt * 128;
        __syncthreads();   // protect KVs reuse (and Qt visibility on iter 0)
        for (int idx = tid; idx < 128 * DH; idx += 256) {
            int d = idx & 63;
            int r = idx >> 6;
            KVs[r * 65 + d] = Kg[(size_t)(j0 + r) * DD + d];
        }
        __syncthreads();

        float acc[4][4];
        #pragma unroll
        for (int i = 0; i < 4; ++i)
            #pragma unroll
            for (int j = 0; j < 4; ++j) acc[i][j] = 0.0f;

        #pragma unroll 8
        for (int d = 0; d < DH; ++d) {
            float qv[4], kv[4];
            #pragma unroll
            for (int ii = 0; ii < 4; ++ii) qv[ii] = Qt[d * 33 + ty * 4 + ii];
            #pragma unroll
            for (int jj = 0; jj < 4; ++jj) kv[jj] = KVs[(tx + jj * 32) * 65 + d];
            #pragma unroll
            for (int ii = 0; ii < 4; ++ii)
                #pragma unroll
                for (int jj = 0; jj < 4; ++jj)
                    acc[ii][jj] = fmaf(qv[ii], kv[jj], acc[ii][jj]);
        }
        #pragma unroll
        for (int ii = 0; ii < 4; ++ii)
            #pragma unroll
            for (int jj = 0; jj < 4; ++jj)
                Ssc[(ty * 4 + ii) * SS + j0 + tx + jj * 32] = acc[ii][jj] * 0.125f;
    }
    __syncthreads();

    // ---- softmax: warp w handles rows 4w..4w+3, 8 lanes per row ----
    {
        const int lane = tid & 31;
        const int w = tid >> 5;
        const int l = lane & 7;
        const int row = w * 4 + (lane >> 3);
        float* srow = Ssc + row * SS;

        float m = -1e30f;
        for (int t = l; t < SS; t += 8) m = fmaxf(m, srow[t]);
        #pragma unroll
        for (int off = 1; off < 8; off <<= 1)
            m = fmaxf(m, __shfl_xor_sync(0xffffffffu, m, off));

        float sum = 0.0f;
        for (int t = l; t < SS; t += 8) {
            float e = __expf(srow[t] - m);
            srow[t] = e;           // keep unnormalized e in smem
            sum += e;
        }
        #pragma unroll
        for (int off = 1; off < 8; off <<= 1)
            sum += __shfl_xor_sync(0xffffffffu, sum, off);
        float inv = 1.0f / sum;
        if (l == 0) invs[row] = inv;

        // write normalized attn to global (single mandatory 256MB write)
        float* arow = attn + ((size_t)(h * BB + b)) * SS * SS + (size_t)(q0 + row) * SS;
        for (int t = l; t < SS; t += 8) arow[t] = srow[t] * inv;
    }
    __syncthreads();

    // ---- context: C[i][jv] = inv[i] * sum_k e[i][k] * V[k][jv] ----
    float acc2[4][2];
    #pragma unroll
    for (int ii = 0; ii < 4; ++ii) { acc2[ii][0] = 0.0f; acc2[ii][1] = 0.0f; }

    for (int kt = 0; kt < SS / 64; ++kt) {
        const int k0 = kt * 64;
        __syncthreads();   // protect KVs reuse
        for (int idx = tid; idx < 64 * DH; idx += 256) {
            int dcol = idx & 63;
            int r = idx >> 6;
            KVs[r * 65 + dcol] = Vg[(size_t)(k0 + r) * DD + dcol];
        }
        __syncthreads();

        #pragma unroll 8
        for (int k = 0; k < 64; ++k) {
            float pv[4], vv[2];
            #pragma unroll
            for (int ii = 0; ii < 4; ++ii) pv[ii] = Ssc[(ty * 4 + ii) * SS + k0 + k];
            #pragma unroll
            for (int jj = 0; jj < 2; ++jj) vv[jj] = KVs[k * 65 + tx + jj * 32];
            #pragma unroll
            for (int ii = 0; ii < 4; ++ii)
                #pragma unroll
                for (int jj = 0; jj < 2; ++jj)
                    acc2[ii][jj] = fmaf(pv[ii], vv[jj], acc2[ii][jj]);
        }
    }

    #pragma unroll
    for (int ii = 0; ii < 4; ++ii) {
        int i = ty * 4 + ii;
        float inv = invs[i];
        #pragma unroll
        for (int jj = 0; jj < 2; ++jj) {
            ctx[(size_t)b * SS * DD + (size_t)(q0 + i) * DD + h * DH + tx + jj * 32] =
                acc2[ii][jj] * inv;
        }
    }
}

// ---------------------------------------------------------------------------
extern "C" void kernel_launch(void* const* d_in, const int* in_sizes, int n_in,
                              void* d_out, int out_size)
{
    const float* query = (const float*)d_in[0];
    const float* key   = (const float*)d_in[1];
    const float* value = (const float*)d_in[2];
    const float* Wq    = (const float*)d_in[3];
    const float* bq    = (const float*)d_in[4];
    const float* Wk    = (const float*)d_in[5];
    const float* bk    = (const float*)d_in[6];
    const float* Wv    = (const float*)d_in[7];
    const float* bv    = (const float*)d_in[8];

    float* out  = (float*)d_out;
    float* ctx  = out;                               // (B, Sq, D)
    float* attn = out + (size_t)BB * SS * DD;        // (H*B, Sq, Sk)

    // Kernel 1: QKV projections
    dim3 g1(GM_N / 64, GM_M / 64, 3);
    qkv_proj_kernel<<<g1, 256>>>(query, key, value, Wq, Wk, Wv, bq, bk, bv);

    // Kernel 2: attention
    const int SMEM_BYTES = (QROWS * SS + DH * 33 + 128 * 65 + 32) * (int)sizeof(float);
    cudaFuncSetAttribute(attn_kernel, cudaFuncAttributeMaxDynamicSharedMemorySize, SMEM_BYTES);
    attn_kernel<<<dim3(SS / QROWS, HH, BB), 256, SMEM_BYTES>>>(ctx, attn);
}

// round 3
// speedup vs baseline: 1.2284x; 1.2284x over previous
#include <cuda_runtime.h>
#include <cuda_bf16.h>
#include <cstdint>
#include <math.h>

// ---------------------------------------------------------------------------
// Problem constants
// ---------------------------------------------------------------------------
#define BB 4
#define SS 1024
#define DD 1024
#define HH 16
#define DH 64
#define GM_M (BB*SS)   // 4096
#define QROWS 32

// ---------------------------------------------------------------------------
// Device scratch
// ---------------------------------------------------------------------------
__device__ float g_Q[GM_M * DD];
__device__ float g_K[GM_M * DD];
__device__ float g_V[GM_M * DD];
__device__ __nv_bfloat16 g_Xhi[3][GM_M * DD];   // q,k,v inputs split hi
__device__ __nv_bfloat16 g_Xlo[3][GM_M * DD];   // q,k,v inputs split lo
__device__ __nv_bfloat16 g_Wthi[3][DD * DD];    // W transposed [n][k] hi
__device__ __nv_bfloat16 g_Wtlo[3][DD * DD];    // W transposed [n][k] lo

// ---------------------------------------------------------------------------
// Portable tensor-core helpers (sm_80+ PTX; compiles for plain sm_103)
// ---------------------------------------------------------------------------
__device__ __forceinline__ uint32_t smem_u32(const void* p) {
    uint32_t a;
    asm("{ .reg .u64 t; cvta.to.shared.u64 t, %1; cvt.u32.u64 %0, t; }" : "=r"(a) : "l"(p));
    return a;
}

#define LDSM_X4(r0, r1, r2, r3, addr) \
    asm volatile("ldmatrix.sync.aligned.m8n8.x4.shared.b16 {%0,%1,%2,%3}, [%4];" \
        : "=r"(r0), "=r"(r1), "=r"(r2), "=r"(r3) : "r"(addr))

#define MMA16816(d, a, b) \
    asm volatile("mma.sync.aligned.m16n8k16.row.col.f32.bf16.bf16.f32 " \
        "{%0,%1,%2,%3}, {%4,%5,%6,%7}, {%8,%9}, {%0,%1,%2,%3};" \
        : "+f"((d)[0]), "+f"((d)[1]), "+f"((d)[2]), "+f"((d)[3]) \
        : "r"((a)[0]), "r"((a)[1]), "r"((a)[2]), "r"((a)[3]), \
          "r"((b)[0]), "r"((b)[1]))

__device__ __forceinline__ void cp16(uint32_t saddr, const void* g) {
    asm volatile("cp.async.ca.shared.global [%0], [%1], 16;" :: "r"(saddr), "l"(g));
}

// ---------------------------------------------------------------------------
// Kernel: split fp32 -> bf16 hi/lo (for q,k,v inputs)
// ---------------------------------------------------------------------------
__global__ __launch_bounds__(256) void conv_split_kernel(const float4* __restrict__ src, int z)
{
    __nv_bfloat162* hi = reinterpret_cast<__nv_bfloat162*>(g_Xhi[z]);
    __nv_bfloat162* lo = reinterpret_cast<__nv_bfloat162*>(g_Xlo[z]);
    const int n4 = GM_M * DD / 4;
    for (int i = blockIdx.x * blockDim.x + threadIdx.x; i < n4; i += gridDim.x * blockDim.x) {
        float4 f = src[i];
        __nv_bfloat16 h0 = __float2bfloat16(f.x), h1 = __float2bfloat16(f.y);
        __nv_bfloat16 h2 = __float2bfloat16(f.z), h3 = __float2bfloat16(f.w);
        __nv_bfloat16 l0 = __float2bfloat16(f.x - __bfloat162float(h0));
        __nv_bfloat16 l1 = __float2bfloat16(f.y - __bfloat162float(h1));
        __nv_bfloat16 l2 = __float2bfloat16(f.z - __bfloat162float(h2));
        __nv_bfloat16 l3 = __float2bfloat16(f.w - __bfloat162float(h3));
        hi[2*i]   = __halves2bfloat162(h0, h1);
        hi[2*i+1] = __halves2bfloat162(h2, h3);
        lo[2*i]   = __halves2bfloat162(l0, l1);
        lo[2*i+1] = __halves2bfloat162(l2, l3);
    }
}

// ---------------------------------------------------------------------------
// Kernel: transpose + split W [k][n] -> Wt hi/lo [n][k]
// ---------------------------------------------------------------------------
__global__ __launch_bounds__(256) void conv_wt_kernel(
    const float* __restrict__ Wq, const float* __restrict__ Wk, const float* __restrict__ Wv)
{
    __shared__ float tile[32][33];
    int z = blockIdx.z;
    const float* W = (z == 0) ? Wq : (z == 1) ? Wk : Wv;
    __nv_bfloat16* Whi = g_Wthi[z];
    __nv_bfloat16* Wlo = g_Wtlo[z];

    int bx = blockIdx.x * 32;   // n block
    int by = blockIdx.y * 32;   // k block
    int tx = threadIdx.x;       // 0..31
    int ty = threadIdx.y;       // 0..7

    #pragma unroll
    for (int r = 0; r < 4; ++r) {
        int k = by + ty + r * 8;
        tile[ty + r * 8][tx] = W[(size_t)k * DD + bx + tx];
    }
    __syncthreads();
    #pragma unroll
    for (int r = 0; r < 4; ++r) {
        int n = bx + ty + r * 8;
        int k = by + tx;
        float v = tile[tx][ty + r * 8];
        __nv_bfloat16 h = __float2bfloat16(v);
        __nv_bfloat16 l = __float2bfloat16(v - __bfloat162float(h));
        Whi[(size_t)n * DD + k] = h;
        Wlo[(size_t)n * DD + k] = l;
    }
}

// ---------------------------------------------------------------------------
// Kernel: HMMA projection GEMM.  Out[4096,1024] = X @ W + bias  (z selects).
// CTA 128x128, BK=32, 8 warps (4 M x 2 N), warp tile 32x64.
// Split-bf16: acc += Ah*Bh + Ah*Bl + Al*Bh.
// Smem rows padded to 80B stride (conflict-free ldmatrix).
// 2-stage cp.async pipeline.
// ---------------------------------------------------------------------------
#define PROJ_STAGE_BYTES 40960            // 4 arrays * 128 rows * 80 B
#define PROJ_SMEM_BYTES  (2 * PROJ_STAGE_BYTES)

__global__ __launch_bounds__(256) void proj_mma_kernel(
    const float* __restrict__ bq, const float* __restrict__ bk,
    const float* __restrict__ bv)
{
    extern __shared__ char smc[];
    const uint32_t smb = smem_u32(smc);
    const int tid  = threadIdx.x;
    const int lane = tid & 31;
    const int wid  = tid >> 5;
    const int wm   = wid & 3;      // 0..3 (M)
    const int wn   = wid >> 2;     // 0..1 (N)
    const int z  = blockIdx.z;
    const int n0 = blockIdx.x * 128;
    const int m0 = blockIdx.y * 128;

    const __nv_bfloat16* Xhi = g_Xhi[z];
    const __nv_bfloat16* Xlo = g_Xlo[z];
    const __nv_bfloat16* Whi = g_Wthi[z];
    const __nv_bfloat16* Wlo = g_Wtlo[z];
    const float* bias = (z == 0) ? bq : (z == 1) ? bk : bv;
    float* Out = (z == 0) ? g_Q : (z == 1) ? g_K : g_V;

    // per-thread global load coords (2 x 16B chunks per array per stage)
    const int l_row[2] = { (tid + 0)   >> 2, (tid + 256) >> 2 };
    const int l_seg[2] = { (tid + 0)   & 3,  (tid + 256) & 3  };

    float acc[2][8][4];
    #pragma unroll
    for (int f = 0; f < 2; ++f)
        #pragma unroll
        for (int j = 0; j < 8; ++j)
            #pragma unroll
            for (int c = 0; c < 4; ++c) acc[f][j][c] = 0.0f;

    // ---- issue stage 0 ----
    {
        const int k0 = 0;
        uint32_t sb = smb;
        #pragma unroll
        for (int t = 0; t < 2; ++t) {
            uint32_t so = (uint32_t)(l_row[t] * 80 + l_seg[t] * 16);
            size_t ga = (size_t)(m0 + l_row[t]) * DD + k0 + l_seg[t] * 8;
            size_t gb = (size_t)(n0 + l_row[t]) * DD + k0 + l_seg[t] * 8;
            cp16(sb +         so, Xhi + ga);
            cp16(sb + 10240 + so, Xlo + ga);
            cp16(sb + 20480 + so, Whi + gb);
            cp16(sb + 30720 + so, Wlo + gb);
        }
        asm volatile("cp.async.commit_group;" ::: "memory");
    }

    // ldmatrix lane addressing (constant across stages, only base varies)
    const uint32_t a_off =
        (uint32_t)((wm * 32 + (lane & 15)) * 80 + (lane >> 4) * 16);
    const int bg = lane >> 3;     // 0..3
    const uint32_t b_off =
        (uint32_t)((wn * 64 + (bg >> 1) * 8 + (lane & 7)) * 80 + (bg & 1) * 16);

    for (int i = 0; i < 32; ++i) {
        if (i < 31) {
            const int k0 = (i + 1) * 32;
            uint32_t sb = smb + ((i + 1) & 1) * PROJ_STAGE_BYTES;
            #pragma unroll
            for (int t = 0; t < 2; ++t) {
                uint32_t so = (uint32_t)(l_row[t] * 80 + l_seg[t] * 16);
                size_t ga = (size_t)(m0 + l_row[t]) * DD + k0 + l_seg[t] * 8;
                size_t gb = (size_t)(n0 + l_row[t]) * DD + k0 + l_seg[t] * 8;
                cp16(sb +         so, Xhi + ga);
                cp16(sb + 10240 + so, Xlo + ga);
                cp16(sb + 20480 + so, Whi + gb);
                cp16(sb + 30720 + so, Wlo + gb);
            }
            asm volatile("cp.async.commit_group;" ::: "memory");
            asm volatile("cp.async.wait_group 1;" ::: "memory");
        } else {
            asm volatile("cp.async.wait_group 0;" ::: "memory");
        }
        __syncthreads();

        const uint32_t sb = smb + (i & 1) * PROJ_STAGE_BYTES;
        #pragma unroll
        for (int s = 0; s < 2; ++s) {
            const uint32_t ks = (uint32_t)(s * 32);
            uint32_t ah[2][4], al[2][4];
            #pragma unroll
            for (int f = 0; f < 2; ++f) {
                uint32_t aaddr = sb + a_off + (uint32_t)(f * 16 * 80) + ks;
                LDSM_X4(ah[f][0], ah[f][1], ah[f][2], ah[f][3], aaddr);
                LDSM_X4(al[f][0], al[f][1], al[f][2], al[f][3], aaddr + 10240);
            }
            uint32_t bh[4][4], bl[4][4];
            #pragma unroll
            for (int nf = 0; nf < 4; ++nf) {
                uint32_t baddr = sb + 20480 + b_off + (uint32_t)(nf * 16 * 80) + ks;
                LDSM_X4(bh[nf][0], bh[nf][1], bh[nf][2], bh[nf][3], baddr);
                LDSM_X4(bl[nf][0], bl[nf][1], bl[nf][2], bl[nf][3], baddr + 10240);
            }
            #pragma unroll
            for (int f = 0; f < 2; ++f) {
                #pragma unroll
                for (int j = 0; j < 8; ++j) {
                    uint32_t bfh[2] = { bh[j >> 1][(j & 1) * 2], bh[j >> 1][(j & 1) * 2 + 1] };
                    uint32_t bfl[2] = { bl[j >> 1][(j & 1) * 2], bl[j >> 1][(j & 1) * 2 + 1] };
                    MMA16816(acc[f][j], ah[f], bfh);
                    MMA16816(acc[f][j], ah[f], bfl);
                    MMA16816(acc[f][j], al[f], bfh);
                }
            }
        }
        __syncthreads();
    }

    // ---- epilogue: fragments -> global fp32 + bias ----
    const int er = m0 + wm * 32 + (lane >> 2);
    const int ec = n0 + wn * 64 + (lane & 3) * 2;
    #pragma unroll
    for (int f = 0; f < 2; ++f) {
        #pragma unroll
        for (int j = 0; j < 8; ++j) {
            int row = er + f * 16;
            int col = ec + j * 8;
            float b0 = __ldg(bias + col);
            float b1 = __ldg(bias + col + 1);
            float2 v0 = { acc[f][j][0] + b0, acc[f][j][1] + b1 };
            float2 v1 = { acc[f][j][2] + b0, acc[f][j][3] + b1 };
            *(float2*)(Out + (size_t)row * DD + col)       = v0;
            *(float2*)(Out + (size_t)(row + 8) * DD + col) = v1;
        }
    }
}

// ---------------------------------------------------------------------------
// Kernel: attention (unchanged — fp32, smem-resident score tile)
// ---------------------------------------------------------------------------
__global__ __launch_bounds__(256) void attn_kernel(
    float* __restrict__ ctx, float* __restrict__ attn)
{
    extern __shared__ float smf[];
    float* Ssc  = smf;
    float* Qt   = Ssc + QROWS * SS;
    float* KVs  = Qt + DH * 33;
    float* invs = KVs + 128 * 65;

    const int q0 = blockIdx.x * QROWS;
    const int h  = blockIdx.y;
    const int b  = blockIdx.z;
    const int tid = threadIdx.x;
    const int tx = tid & 31;
    const int ty = tid >> 5;

    const float* Qg = g_Q + (size_t)b * SS * DD + h * DH;
    const float* Kg = g_K + (size_t)b * SS * DD + h * DH;
    const float* Vg = g_V + (size_t)b * SS * DD + h * DH;

    for (int idx = tid; idx < QROWS * DH; idx += 256) {
        int d = idx & 63;
        int i = idx >> 6;
        Qt[d * 33 + i] = Qg[(size_t)(q0 + i) * DD + d];
    }

    for (int jt = 0; jt < SS / 128; ++jt) {
        const int j0 = jt * 128;
        __syncthreads();
        for (int idx = tid; idx < 128 * DH; idx += 256) {
            int d = idx & 63;
            int r = idx >> 6;
            KVs[r * 65 + d] = Kg[(size_t)(j0 + r) * DD + d];
        }
        __syncthreads();

        float acc[4][4];
        #pragma unroll
        for (int i = 0; i < 4; ++i)
            #pragma unroll
            for (int j = 0; j < 4; ++j) acc[i][j] = 0.0f;

        #pragma unroll 8
        for (int d = 0; d < DH; ++d) {
            float qv[4], kv[4];
            #pragma unroll
            for (int ii = 0; ii < 4; ++ii) qv[ii] = Qt[d * 33 + ty * 4 + ii];
            #pragma unroll
            for (int jj = 0; jj < 4; ++jj) kv[jj] = KVs[(tx + jj * 32) * 65 + d];
            #pragma unroll
            for (int ii = 0; ii < 4; ++ii)
                #pragma unroll
                for (int jj = 0; jj < 4; ++jj)
                    acc[ii][jj] = fmaf(qv[ii], kv[jj], acc[ii][jj]);
        }
        #pragma unroll
        for (int ii = 0; ii < 4; ++ii)
            #pragma unroll
            for (int jj = 0; jj < 4; ++jj)
                Ssc[(ty * 4 + ii) * SS + j0 + tx + jj * 32] = acc[ii][jj] * 0.125f;
    }
    __syncthreads();

    {
        const int lane = tid & 31;
        const int w = tid >> 5;
        const int l = lane & 7;
        const int row = w * 4 + (lane >> 3);
        float* srow = Ssc + row * SS;

        float m = -1e30f;
        for (int t = l; t < SS; t += 8) m = fmaxf(m, srow[t]);
        #pragma unroll
        for (int off = 1; off < 8; off <<= 1)
            m = fmaxf(m, __shfl_xor_sync(0xffffffffu, m, off));

        float sum = 0.0f;
        for (int t = l; t < SS; t += 8) {
            float e = __expf(srow[t] - m);
            srow[t] = e;
            sum += e;
        }
        #pragma unroll
        for (int off = 1; off < 8; off <<= 1)
            sum += __shfl_xor_sync(0xffffffffu, sum, off);
        float inv = 1.0f / sum;
        if (l == 0) invs[row] = inv;

        float* arow = attn + ((size_t)(h * BB + b)) * SS * SS + (size_t)(q0 + row) * SS;
        for (int t = l; t < SS; t += 8) arow[t] = srow[t] * inv;
    }
    __syncthreads();

    float acc2[4][2];
    #pragma unroll
    for (int ii = 0; ii < 4; ++ii) { acc2[ii][0] = 0.0f; acc2[ii][1] = 0.0f; }

    for (int kt = 0; kt < SS / 64; ++kt) {
        const int k0 = kt * 64;
        __syncthreads();
        for (int idx = tid; idx < 64 * DH; idx += 256) {
            int dcol = idx & 63;
            int r = idx >> 6;
            KVs[r * 65 + dcol] = Vg[(size_t)(k0 + r) * DD + dcol];
        }
        __syncthreads();

        #pragma unroll 8
        for (int k = 0; k < 64; ++k) {
            float pv[4], vv[2];
            #pragma unroll
            for (int ii = 0; ii < 4; ++ii) pv[ii] = Ssc[(ty * 4 + ii) * SS + k0 + k];
            #pragma unroll
            for (int jj = 0; jj < 2; ++jj) vv[jj] = KVs[k * 65 + tx + jj * 32];
            #pragma unroll
            for (int ii = 0; ii < 4; ++ii)
                #pragma unroll
                for (int jj = 0; jj < 2; ++jj)
                    acc2[ii][jj] = fmaf(pv[ii], vv[jj], acc2[ii][jj]);
        }
    }

    #pragma unroll
    for (int ii = 0; ii < 4; ++ii) {
        int i = ty * 4 + ii;
        float inv = invs[i];
        #pragma unroll
        for (int jj = 0; jj < 2; ++jj) {
            ctx[(size_t)b * SS * DD + (size_t)(q0 + i) * DD + h * DH + tx + jj * 32] =
                acc2[ii][jj] * inv;
        }
    }
}

// ---------------------------------------------------------------------------
extern "C" void kernel_launch(void* const* d_in, const int* in_sizes, int n_in,
                              void* d_out, int out_size)
{
    const float* query = (const float*)d_in[0];
    const float* key   = (const float*)d_in[1];
    const float* value = (const float*)d_in[2];
    const float* Wq    = (const float*)d_in[3];
    const float* bq    = (const float*)d_in[4];
    const float* Wk    = (const float*)d_in[5];
    const float* bk    = (const float*)d_in[6];
    const float* Wv    = (const float*)d_in[7];
    const float* bv    = (const float*)d_in[8];

    float* out  = (float*)d_out;
    float* ctx  = out;
    float* attn = out + (size_t)BB * SS * DD;

    // 1) split inputs to bf16 hi/lo
    conv_split_kernel<<<1024, 256>>>((const float4*)query, 0);
    conv_split_kernel<<<1024, 256>>>((const float4*)key,   1);
    conv_split_kernel<<<1024, 256>>>((const float4*)value, 2);
    // 2) transpose + split weights
    conv_wt_kernel<<<dim3(32, 32, 3), dim3(32, 8)>>>(Wq, Wk, Wv);
    // 3) HMMA projection GEMMs
    cudaFuncSetAttribute(proj_mma_kernel, cudaFuncAttributeMaxDynamicSharedMemorySize,
                         PROJ_SMEM_BYTES);
    proj_mma_kernel<<<dim3(8, 32, 3), 256, PROJ_SMEM_BYTES>>>(bq, bk, bv);
    // 4) attention
    const int ATTN_SMEM = (QROWS * SS + DH * 33 + 128 * 65 + 32) * (int)sizeof(float);
    cudaFuncSetAttribute(attn_kernel, cudaFuncAttributeMaxDynamicSharedMemorySize, ATTN_SMEM);
    attn_kernel<<<dim3(SS / QROWS, HH, BB), 256, ATTN_SMEM>>>(ctx, attn);
}

// round 4
// speedup vs baseline: 3.3204x; 2.7031x over previous
#include <cuda_runtime.h>
#include <cuda_bf16.h>
#include <cstdint>
#include <math.h>

// ---------------------------------------------------------------------------
// Problem constants
// ---------------------------------------------------------------------------
#define BB 4
#define SS 1024
#define DD 1024
#define HH 16
#define DH 64
#define GM_M (BB*SS)   // 4096

// ---------------------------------------------------------------------------
// Device scratch
// ---------------------------------------------------------------------------
__device__ float g_Q[GM_M * DD];
__device__ float g_K[GM_M * DD];
__device__ float g_V[GM_M * DD];
__device__ __nv_bfloat16 g_Xhi[3][GM_M * DD];
__device__ __nv_bfloat16 g_Xlo[3][GM_M * DD];
__device__ __nv_bfloat16 g_Wthi[3][DD * DD];
__device__ __nv_bfloat16 g_Wtlo[3][DD * DD];
// head-major attention operands
__device__ __nv_bfloat16 g_Qh[BB * HH * SS * DH];
__device__ __nv_bfloat16 g_Ql[BB * HH * SS * DH];
__device__ __nv_bfloat16 g_Kh[BB * HH * SS * DH];
__device__ __nv_bfloat16 g_Kl[BB * HH * SS * DH];
__device__ __nv_bfloat16 g_Vth[BB * HH * DH * SS];   // [bh][d][s]
__device__ __nv_bfloat16 g_Vtl[BB * HH * DH * SS];

// ---------------------------------------------------------------------------
// Helpers
// ---------------------------------------------------------------------------
__device__ __forceinline__ uint32_t smem_u32(const void* p) {
    uint32_t a;
    asm("{ .reg .u64 t; cvta.to.shared.u64 t, %1; cvt.u32.u64 %0, t; }" : "=r"(a) : "l"(p));
    return a;
}
#define LDSM_X4(r0, r1, r2, r3, addr) \
    asm volatile("ldmatrix.sync.aligned.m8n8.x4.shared.b16 {%0,%1,%2,%3}, [%4];" \
        : "=r"(r0), "=r"(r1), "=r"(r2), "=r"(r3) : "r"(addr))
#define MMA16816(d, a, b) \
    asm volatile("mma.sync.aligned.m16n8k16.row.col.f32.bf16.bf16.f32 " \
        "{%0,%1,%2,%3}, {%4,%5,%6,%7}, {%8,%9}, {%0,%1,%2,%3};" \
        : "+f"((d)[0]), "+f"((d)[1]), "+f"((d)[2]), "+f"((d)[3]) \
        : "r"((a)[0]), "r"((a)[1]), "r"((a)[2]), "r"((a)[3]), \
          "r"((b)[0]), "r"((b)[1]))
__device__ __forceinline__ void cp16(uint32_t saddr, const void* g) {
    asm volatile("cp.async.ca.shared.global [%0], [%1], 16;" :: "r"(saddr), "l"(g));
}
#define CP_COMMIT() asm volatile("cp.async.commit_group;" ::: "memory")
#define CP_WAIT(n)  asm volatile("cp.async.wait_group %0;" :: "n"(n) : "memory")

__device__ __forceinline__ void splitf(float x, __nv_bfloat16& h, __nv_bfloat16& l) {
    h = __float2bfloat16(x);
    l = __float2bfloat16(x - __bfloat162float(h));
}
__device__ __forceinline__ void split2(float2 p, uint32_t& hi, uint32_t& lo) {
    __nv_bfloat16 hx, lx, hy, ly;
    splitf(p.x, hx, lx); splitf(p.y, hy, ly);
    __nv_bfloat162 h2 = __halves2bfloat162(hx, hy);
    __nv_bfloat162 l2 = __halves2bfloat162(lx, ly);
    hi = *reinterpret_cast<uint32_t*>(&h2);
    lo = *reinterpret_cast<uint32_t*>(&l2);
}

// ---------------------------------------------------------------------------
// Kernel: split fp32 -> bf16 hi/lo (q,k,v inputs)
// ---------------------------------------------------------------------------
__global__ __launch_bounds__(256) void conv_split_kernel(const float4* __restrict__ src, int z)
{
    __nv_bfloat162* hi = reinterpret_cast<__nv_bfloat162*>(g_Xhi[z]);
    __nv_bfloat162* lo = reinterpret_cast<__nv_bfloat162*>(g_Xlo[z]);
    const int n4 = GM_M * DD / 4;
    for (int i = blockIdx.x * blockDim.x + threadIdx.x; i < n4; i += gridDim.x * blockDim.x) {
        float4 f = src[i];
        __nv_bfloat16 h0, l0, h1, l1, h2, l2, h3, l3;
        splitf(f.x, h0, l0); splitf(f.y, h1, l1);
        splitf(f.z, h2, l2); splitf(f.w, h3, l3);
        hi[2*i]   = __halves2bfloat162(h0, h1);
        hi[2*i+1] = __halves2bfloat162(h2, h3);
        lo[2*i]   = __halves2bfloat162(l0, l1);
        lo[2*i+1] = __halves2bfloat162(l2, l3);
    }
}

// ---------------------------------------------------------------------------
// Kernel: transpose + split W [k][n] -> Wt hi/lo [n][k]
// ---------------------------------------------------------------------------
__global__ __launch_bounds__(256) void conv_wt_kernel(
    const float* __restrict__ Wq, const float* __restrict__ Wk, const float* __restrict__ Wv)
{
    __shared__ float tile[32][33];
    int z = blockIdx.z;
    const float* W = (z == 0) ? Wq : (z == 1) ? Wk : Wv;
    __nv_bfloat16* Whi = g_Wthi[z];
    __nv_bfloat16* Wlo = g_Wtlo[z];

    int bx = blockIdx.x * 32;
    int by = blockIdx.y * 32;
    int tx = threadIdx.x;
    int ty = threadIdx.y;

    #pragma unroll
    for (int r = 0; r < 4; ++r) {
        int k = by + ty + r * 8;
        tile[ty + r * 8][tx] = W[(size_t)k * DD + bx + tx];
    }
    __syncthreads();
    #pragma unroll
    for (int r = 0; r < 4; ++r) {
        int n = bx + ty + r * 8;
        int k = by + tx;
        float v = tile[tx][ty + r * 8];
        __nv_bfloat16 h, l;
        splitf(v, h, l);
        Whi[(size_t)n * DD + k] = h;
        Wlo[(size_t)n * DD + k] = l;
    }
}

// ---------------------------------------------------------------------------
// Kernel: HMMA projection GEMM (unchanged from round 3)
// ---------------------------------------------------------------------------
#define PROJ_STAGE_BYTES 40960
#define PROJ_SMEM_BYTES  (2 * PROJ_STAGE_BYTES)

__global__ __launch_bounds__(256) void proj_mma_kernel(
    const float* __restrict__ bq, const float* __restrict__ bk,
    const float* __restrict__ bv)
{
    extern __shared__ char smc[];
    const uint32_t smb = smem_u32(smc);
    const int tid  = threadIdx.x;
    const int lane = tid & 31;
    const int wid  = tid >> 5;
    const int wm   = wid & 3;
    const int wn   = wid >> 2;
    const int z  = blockIdx.z;
    const int n0 = blockIdx.x * 128;
    const int m0 = blockIdx.y * 128;

    const __nv_bfloat16* Xhi = g_Xhi[z];
    const __nv_bfloat16* Xlo = g_Xlo[z];
    const __nv_bfloat16* Whi = g_Wthi[z];
    const __nv_bfloat16* Wlo = g_Wtlo[z];
    const float* bias = (z == 0) ? bq : (z == 1) ? bk : bv;
    float* Out = (z == 0) ? g_Q : (z == 1) ? g_K : g_V;

    const int l_row[2] = { (tid + 0) >> 2, (tid + 256) >> 2 };
    const int l_seg[2] = { (tid + 0) & 3,  (tid + 256) & 3  };

    float acc[2][8][4];
    #pragma unroll
    for (int f = 0; f < 2; ++f)
        #pragma unroll
        for (int j = 0; j < 8; ++j)
            #pragma unroll
            for (int c = 0; c < 4; ++c) acc[f][j][c] = 0.0f;

    {
        uint32_t sb = smb;
        #pragma unroll
        for (int t = 0; t < 2; ++t) {
            uint32_t so = (uint32_t)(l_row[t] * 80 + l_seg[t] * 16);
            size_t ga = (size_t)(m0 + l_row[t]) * DD + l_seg[t] * 8;
            size_t gb = (size_t)(n0 + l_row[t]) * DD + l_seg[t] * 8;
            cp16(sb +         so, Xhi + ga);
            cp16(sb + 10240 + so, Xlo + ga);
            cp16(sb + 20480 + so, Whi + gb);
            cp16(sb + 30720 + so, Wlo + gb);
        }
        CP_COMMIT();
    }

    const uint32_t a_off =
        (uint32_t)((wm * 32 + (lane & 15)) * 80 + (lane >> 4) * 16);
    const int bg = lane >> 3;
    const uint32_t b_off =
        (uint32_t)((wn * 64 + (bg >> 1) * 8 + (lane & 7)) * 80 + (bg & 1) * 16);

    for (int i = 0; i < 32; ++i) {
        if (i < 31) {
            const int k0 = (i + 1) * 32;
            uint32_t sb = smb + ((i + 1) & 1) * PROJ_STAGE_BYTES;
            #pragma unroll
            for (int t = 0; t < 2; ++t) {
                uint32_t so = (uint32_t)(l_row[t] * 80 + l_seg[t] * 16);
                size_t ga = (size_t)(m0 + l_row[t]) * DD + k0 + l_seg[t] * 8;
                size_t gb = (size_t)(n0 + l_row[t]) * DD + k0 + l_seg[t] * 8;
                cp16(sb +         so, Xhi + ga);
                cp16(sb + 10240 + so, Xlo + ga);
                cp16(sb + 20480 + so, Whi + gb);
                cp16(sb + 30720 + so, Wlo + gb);
            }
            CP_COMMIT();
            CP_WAIT(1);
        } else {
            CP_WAIT(0);
        }
        __syncthreads();

        const uint32_t sb = smb + (i & 1) * PROJ_STAGE_BYTES;
        #pragma unroll
        for (int s = 0; s < 2; ++s) {
            const uint32_t ks = (uint32_t)(s * 32);
            uint32_t ah[2][4], al[2][4];
            #pragma unroll
            for (int f = 0; f < 2; ++f) {
                uint32_t aaddr = sb + a_off + (uint32_t)(f * 16 * 80) + ks;
                LDSM_X4(ah[f][0], ah[f][1], ah[f][2], ah[f][3], aaddr);
                LDSM_X4(al[f][0], al[f][1], al[f][2], al[f][3], aaddr + 10240);
            }
            uint32_t bh[4][4], bl[4][4];
            #pragma unroll
            for (int nf = 0; nf < 4; ++nf) {
                uint32_t baddr = sb + 20480 + b_off + (uint32_t)(nf * 16 * 80) + ks;
                LDSM_X4(bh[nf][0], bh[nf][1], bh[nf][2], bh[nf][3], baddr);
                LDSM_X4(bl[nf][0], bl[nf][1], bl[nf][2], bl[nf][3], baddr + 10240);
            }
            #pragma unroll
            for (int f = 0; f < 2; ++f) {
                #pragma unroll
                for (int j = 0; j < 8; ++j) {
                    uint32_t bfh[2] = { bh[j >> 1][(j & 1) * 2], bh[j >> 1][(j & 1) * 2 + 1] };
                    uint32_t bfl[2] = { bl[j >> 1][(j & 1) * 2], bl[j >> 1][(j & 1) * 2 + 1] };
                    MMA16816(acc[f][j], ah[f], bfh);
                    MMA16816(acc[f][j], ah[f], bfl);
                    MMA16816(acc[f][j], al[f], bfh);
                }
            }
        }
        __syncthreads();
    }

    const int er = m0 + wm * 32 + (lane >> 2);
    const int ec = n0 + wn * 64 + (lane & 3) * 2;
    #pragma unroll
    for (int f = 0; f < 2; ++f) {
        #pragma unroll
        for (int j = 0; j < 8; ++j) {
            int row = er + f * 16;
            int col = ec + j * 8;
            float b0 = __ldg(bias + col);
            float b1 = __ldg(bias + col + 1);
            float2 v0 = { acc[f][j][0] + b0, acc[f][j][1] + b1 };
            float2 v1 = { acc[f][j][2] + b0, acc[f][j][3] + b1 };
            *(float2*)(Out + (size_t)row * DD + col)       = v0;
            *(float2*)(Out + (size_t)(row + 8) * DD + col) = v1;
        }
    }
}

// ---------------------------------------------------------------------------
// Kernel: head-major bf16 hi/lo for Q (grid.y=0) and K (grid.y=1)
// out[bh][s][d] = in[(b,s)][h*64+d]
// ---------------------------------------------------------------------------
__global__ __launch_bounds__(256) void conv_headify_kernel()
{
    int z = blockIdx.y;
    const float* src = z ? g_K : g_Q;
    __nv_bfloat16* dsth = z ? g_Kh : g_Qh;
    __nv_bfloat16* dstl = z ? g_Kl : g_Ql;

    int gid = blockIdx.x * 256 + threadIdx.x;   // 0..1M-1, 4 elems each
    int d4 = gid & 15;
    int h  = (gid >> 4) & 15;
    int s  = (gid >> 8) & 1023;
    int b  = gid >> 18;
    float4 v = *(const float4*)(src + ((size_t)b * SS + s) * DD + h * 64 + d4 * 4);
    size_t o = (((size_t)(b * HH + h)) * SS + s) * DH + d4 * 4;
    __nv_bfloat16 h0, l0, h1, l1, h2, l2, h3, l3;
    splitf(v.x, h0, l0); splitf(v.y, h1, l1);
    splitf(v.z, h2, l2); splitf(v.w, h3, l3);
    __nv_bfloat162* ph = (__nv_bfloat162*)(dsth + o);
    __nv_bfloat162* pl = (__nv_bfloat162*)(dstl + o);
    ph[0] = __halves2bfloat162(h0, h1); ph[1] = __halves2bfloat162(h2, h3);
    pl[0] = __halves2bfloat162(l0, l1); pl[1] = __halves2bfloat162(l2, l3);
}

// ---------------------------------------------------------------------------
// Kernel: V transpose + split: g_V -> Vt hi/lo [bh][d][s]
// ---------------------------------------------------------------------------
__global__ __launch_bounds__(256) void conv_vt_kernel()
{
    __shared__ float tile[64][33];
    int s0 = blockIdx.x * 32;
    int bh = blockIdx.y;
    int b = bh >> 4, h = bh & 15;
    int tid = threadIdx.x;

    #pragma unroll
    for (int t = 0; t < 2; ++t) {
        int i = tid + t * 256;
        int r = i >> 4, d4 = i & 15;
        float4 v = *(const float4*)(g_V + ((size_t)b * SS + s0 + r) * DD + h * 64 + d4 * 4);
        tile[d4 * 4 + 0][r] = v.x;
        tile[d4 * 4 + 1][r] = v.y;
        tile[d4 * 4 + 2][r] = v.z;
        tile[d4 * 4 + 3][r] = v.w;
    }
    __syncthreads();
    #pragma unroll
    for (int t = 0; t < 2; ++t) {
        int i = tid + t * 256;
        int d = i >> 3, sg = i & 7;
        size_t o = ((size_t)bh * DH + d) * SS + s0 + sg * 4;
        __nv_bfloat16 h0, l0, h1, l1, h2, l2, h3, l3;
        splitf(tile[d][sg * 4 + 0], h0, l0);
        splitf(tile[d][sg * 4 + 1], h1, l1);
        splitf(tile[d][sg * 4 + 2], h2, l2);
        splitf(tile[d][sg * 4 + 3], h3, l3);
        __nv_bfloat162* ph = (__nv_bfloat162*)(g_Vth + o);
        __nv_bfloat162* pl = (__nv_bfloat162*)(g_Vtl + o);
        ph[0] = __halves2bfloat162(h0, h1); ph[1] = __halves2bfloat162(h2, h3);
        pl[0] = __halves2bfloat162(l0, l1); pl[1] = __halves2bfloat162(l2, l3);
    }
}

// ---------------------------------------------------------------------------
// Kernel: attention with HMMA.
// CTA = 32 q-rows x one (b,h). 8 warps.
// Smem layout (bytes):
//   [0,132608)          Ssc fp32, 32 rows, stride 1036 floats (4144 B)
//   [132608,137216)     Q hi  (32 rows x 144 B)
//   [137216,141824)     Q lo
//   [141824,+2*36864)   staging double buffer (K: 128x144 hi + lo; Vt: 64x272 hi + lo)
//   [215552,215680)     invs (32 floats)
// ---------------------------------------------------------------------------
#define SSTR     1036
#define AT_QOFF  132608
#define AT_STG   141824
#define AT_BUF   36864
#define AT_INVS  215552
#define AT_SMEM  215680

__global__ __launch_bounds__(256) void attn_mma_kernel(
    float* __restrict__ ctx, float* __restrict__ attn)
{
    extern __shared__ char smc[];
    float* Ssc  = (float*)smc;
    float* invs = (float*)(smc + AT_INVS);
    const uint32_t smb = smem_u32(smc);
    const int tid = threadIdx.x, lane = tid & 31, wid = tid >> 5;
    const int q0 = blockIdx.x * 32;
    const int h  = blockIdx.y;
    const int b  = blockIdx.z;
    const int bh = b * HH + h;

    // ---- Q tile hi/lo into padded smem ----
    {
        int row = tid >> 3, seg = tid & 7;
        size_t g = ((size_t)bh * SS + q0 + row) * DH + seg * 8;
        *(uint4*)(smc + AT_QOFF + row * 144 + seg * 16)        = *(const uint4*)(g_Qh + g);
        *(uint4*)(smc + AT_QOFF + 4608 + row * 144 + seg * 16) = *(const uint4*)(g_Ql + g);
    }

    const __nv_bfloat16* Kh = g_Kh + (size_t)bh * SS * DH;
    const __nv_bfloat16* Kl = g_Kl + (size_t)bh * SS * DH;

    // ---- issue K chunk 0 ----
    {
        uint32_t sb = smb + AT_STG;
        #pragma unroll
        for (int t = 0; t < 4; ++t) {
            int idx = tid + t * 256;
            int row = idx >> 3, seg = idx & 7;
            uint32_t so = sb + row * 144 + seg * 16;
            cp16(so,         Kh + (size_t)row * DH + seg * 8);
            cp16(so + 18432, Kl + (size_t)row * DH + seg * 8);
        }
        CP_COMMIT();
    }

    // ---- scores ----
    const int wm = wid & 1, wn = wid >> 1;
    const int bg = lane >> 3;
    for (int ic = 0; ic < 8; ++ic) {
        if (ic < 7) {
            uint32_t sb = smb + AT_STG + ((ic + 1) & 1) * AT_BUF;
            const __nv_bfloat16* kh = Kh + (size_t)(ic + 1) * 128 * DH;
            const __nv_bfloat16* kl = Kl + (size_t)(ic + 1) * 128 * DH;
            #pragma unroll
            for (int t = 0; t < 4; ++t) {
                int idx = tid + t * 256;
                int row = idx >> 3, seg = idx & 7;
                uint32_t so = sb + row * 144 + seg * 16;
                cp16(so,         kh + (size_t)row * DH + seg * 8);
                cp16(so + 18432, kl + (size_t)row * DH + seg * 8);
            }
            CP_COMMIT();
            CP_WAIT(1);
        } else {
            CP_WAIT(0);
        }
        __syncthreads();

        uint32_t sb = smb + AT_STG + (ic & 1) * AT_BUF;
        float acc[4][4];
        #pragma unroll
        for (int jj = 0; jj < 4; ++jj)
            #pragma unroll
            for (int c = 0; c < 4; ++c) acc[jj][c] = 0.0f;

        #pragma unroll
        for (int ks = 0; ks < 4; ++ks) {
            uint32_t ah[4], al[4];
            uint32_t aaddr = smb + AT_QOFF + (wm * 16 + (lane & 15)) * 144
                           + (lane >> 4) * 16 + ks * 32;
            LDSM_X4(ah[0], ah[1], ah[2], ah[3], aaddr);
            LDSM_X4(al[0], al[1], al[2], al[3], aaddr + 4608);
            #pragma unroll
            for (int g = 0; g < 2; ++g) {
                uint32_t bhf[4], blf[4];
                uint32_t baddr = sb + (wn * 32 + g * 16 + (bg >> 1) * 8 + (lane & 7)) * 144
                               + (bg & 1) * 16 + ks * 32;
                LDSM_X4(bhf[0], bhf[1], bhf[2], bhf[3], baddr);
                LDSM_X4(blf[0], blf[1], blf[2], blf[3], baddr + 18432);
                #pragma unroll
                for (int j2 = 0; j2 < 2; ++j2) {
                    uint32_t b2h[2] = { bhf[j2 * 2], bhf[j2 * 2 + 1] };
                    uint32_t b2l[2] = { blf[j2 * 2], blf[j2 * 2 + 1] };
                    MMA16816(acc[g * 2 + j2], ah, b2h);
                    MMA16816(acc[g * 2 + j2], ah, b2l);
                    MMA16816(acc[g * 2 + j2], al, b2h);
                }
            }
        }
        int r = wm * 16 + (lane >> 2);
        #pragma unroll
        for (int jj = 0; jj < 4; ++jj) {
            int c = ic * 128 + wn * 32 + (jj >> 1) * 16 + (jj & 1) * 8 + (lane & 3) * 2;
            Ssc[r * SSTR + c]           = acc[jj][0] * 0.125f;
            Ssc[r * SSTR + c + 1]       = acc[jj][1] * 0.125f;
            Ssc[(r + 8) * SSTR + c]     = acc[jj][2] * 0.125f;
            Ssc[(r + 8) * SSTR + c + 1] = acc[jj][3] * 0.125f;
        }
        __syncthreads();
    }

    // ---- prefetch Vt chunk 0 (overlaps softmax) ----
    const __nv_bfloat16* Vh = g_Vth + (size_t)bh * DH * SS;
    const __nv_bfloat16* Vl = g_Vtl + (size_t)bh * DH * SS;
    {
        uint32_t sb = smb + AT_STG;
        #pragma unroll
        for (int t = 0; t < 4; ++t) {
            int idx = tid + t * 256;
            int row = idx >> 4, seg = idx & 15;
            uint32_t so = sb + row * 272 + seg * 16;
            cp16(so,         Vh + (size_t)row * SS + seg * 8);
            cp16(so + 17408, Vl + (size_t)row * SS + seg * 8);
        }
        CP_COMMIT();
    }

    // ---- softmax (unnormalized e kept in Ssc; attn written normalized) ----
    {
        const int l = lane & 7;
        const int row = wid * 4 + (lane >> 3);
        float* srow = Ssc + row * SSTR;

        float m = -1e30f;
        for (int t = l; t < SS; t += 8) m = fmaxf(m, srow[t]);
        #pragma unroll
        for (int off = 1; off < 8; off <<= 1)
            m = fmaxf(m, __shfl_xor_sync(0xffffffffu, m, off));

        float sum = 0.0f;
        for (int t = l; t < SS; t += 8) {
            float e = __expf(srow[t] - m);
            srow[t] = e;
            sum += e;
        }
        #pragma unroll
        for (int off = 1; off < 8; off <<= 1)
            sum += __shfl_xor_sync(0xffffffffu, sum, off);
        float inv = 1.0f / sum;
        if (l == 0) invs[row] = inv;

        float* arow = attn + ((size_t)(h * BB + b)) * SS * SS + (size_t)(q0 + row) * SS;
        for (int t = l; t < SS; t += 8) arow[t] = srow[t] * inv;
    }

    // ---- P @ V via HMMA (split-bf16 P on the fly) ----
    const int wm2 = wid & 1, wn2 = wid >> 1;
    float acc2[2][4];
    #pragma unroll
    for (int j2 = 0; j2 < 2; ++j2)
        #pragma unroll
        for (int c = 0; c < 4; ++c) acc2[j2][c] = 0.0f;

    for (int jc = 0; jc < 8; ++jc) {
        if (jc < 7) {
            uint32_t sb = smb + AT_STG + ((jc + 1) & 1) * AT_BUF;
            const __nv_bfloat16* vh = Vh + (size_t)(jc + 1) * 128;
            const __nv_bfloat16* vl = Vl + (size_t)(jc + 1) * 128;
            #pragma unroll
            for (int t = 0; t < 4; ++t) {
                int idx = tid + t * 256;
                int row = idx >> 4, seg = idx & 15;
                uint32_t so = sb + row * 272 + seg * 16;
                cp16(so,         vh + (size_t)row * SS + seg * 8);
                cp16(so + 17408, vl + (size_t)row * SS + seg * 8);
            }
            CP_COMMIT();
            CP_WAIT(1);
        } else {
            CP_WAIT(0);
        }
        __syncthreads();

        uint32_t sb = smb + AT_STG + (jc & 1) * AT_BUF;
        const int ar = wm2 * 16 + (lane >> 2);
        #pragma unroll
        for (int ks = 0; ks < 8; ++ks) {
            int ac = jc * 128 + ks * 16 + (lane & 3) * 2;
            float2 p00 = *(float2*)&Ssc[ar * SSTR + ac];
            float2 p10 = *(float2*)&Ssc[(ar + 8) * SSTR + ac];
            float2 p01 = *(float2*)&Ssc[ar * SSTR + ac + 8];
            float2 p11 = *(float2*)&Ssc[(ar + 8) * SSTR + ac + 8];
            uint32_t ah[4], al[4];
            split2(p00, ah[0], al[0]);
            split2(p10, ah[1], al[1]);
            split2(p01, ah[2], al[2]);
            split2(p11, ah[3], al[3]);

            uint32_t bhf[4], blf[4];
            uint32_t baddr = sb + (wn2 * 16 + (bg >> 1) * 8 + (lane & 7)) * 272
                           + (bg & 1) * 16 + ks * 32;
            LDSM_X4(bhf[0], bhf[1], bhf[2], bhf[3], baddr);
            LDSM_X4(blf[0], blf[1], blf[2], blf[3], baddr + 17408);
            #pragma unroll
            for (int j2 = 0; j2 < 2; ++j2) {
                uint32_t b2h[2] = { bhf[j2 * 2], bhf[j2 * 2 + 1] };
                uint32_t b2l[2] = { blf[j2 * 2], blf[j2 * 2 + 1] };
                MMA16816(acc2[j2], ah, b2h);
                MMA16816(acc2[j2], ah, b2l);
                MMA16816(acc2[j2], al, b2h);
            }
        }
        __syncthreads();
    }

    // ---- context epilogue ----
    {
        int r = wm2 * 16 + (lane >> 2);
        float inv0 = invs[r];
        float inv1 = invs[r + 8];
        #pragma unroll
        for (int j2 = 0; j2 < 2; ++j2) {
            int c = h * 64 + wn2 * 16 + j2 * 8 + (lane & 3) * 2;
            float2 v0 = { acc2[j2][0] * inv0, acc2[j2][1] * inv0 };
            float2 v1 = { acc2[j2][2] * inv1, acc2[j2][3] * inv1 };
            *(float2*)&ctx[((size_t)b * SS + q0 + r) * DD + c]     = v0;
            *(float2*)&ctx[((size_t)b * SS + q0 + r + 8) * DD + c] = v1;
        }
    }
}

// ---------------------------------------------------------------------------
extern "C" void kernel_launch(void* const* d_in, const int* in_sizes, int n_in,
                              void* d_out, int out_size)
{
    const float* query = (const float*)d_in[0];
    const float* key   = (const float*)d_in[1];
    const float* value = (const float*)d_in[2];
    const float* Wq    = (const float*)d_in[3];
    const float* bq    = (const float*)d_in[4];
    const float* Wk    = (const float*)d_in[5];
    const float* bk    = (const float*)d_in[6];
    const float* Wv    = (const float*)d_in[7];
    const float* bv    = (const float*)d_in[8];

    float* out  = (float*)d_out;
    float* ctx  = out;
    float* attn = out + (size_t)BB * SS * DD;

    conv_split_kernel<<<1024, 256>>>((const float4*)query, 0);
    conv_split_kernel<<<1024, 256>>>((const float4*)key,   1);
    conv_split_kernel<<<1024, 256>>>((const float4*)value, 2);
    conv_wt_kernel<<<dim3(32, 32, 3), dim3(32, 8)>>>(Wq, Wk, Wv);

    cudaFuncSetAttribute(proj_mma_kernel, cudaFuncAttributeMaxDynamicSharedMemorySize,
                         PROJ_SMEM_BYTES);
    proj_mma_kernel<<<dim3(8, 32, 3), 256, PROJ_SMEM_BYTES>>>(bq, bk, bv);

    conv_headify_kernel<<<dim3(4096, 2), 256>>>();
    conv_vt_kernel<<<dim3(SS / 32, BB * HH), 256>>>();

    cudaFuncSetAttribute(attn_mma_kernel, cudaFuncAttributeMaxDynamicSharedMemorySize,
                         AT_SMEM);
    attn_mma_kernel<<<dim3(SS / 32, HH, BB), 256, AT_SMEM>>>(ctx, attn);
}

// round 5
// speedup vs baseline: 3.3729x; 1.0158x over previous
#include <cuda_runtime.h>
#include <cuda_bf16.h>
#include <cstdint>
#include <math.h>

// ---------------------------------------------------------------------------
// Problem constants
// ---------------------------------------------------------------------------
#define BB 4
#define SS 1024
#define DD 1024
#define HH 16
#define DH 64
#define GM_M (BB*SS)   // 4096

// ---------------------------------------------------------------------------
// Device scratch
// ---------------------------------------------------------------------------
__device__ float g_V[GM_M * DD];                 // fp32 V (for transpose pass)
__device__ __nv_bfloat16 g_Xhi[3][GM_M * DD];
__device__ __nv_bfloat16 g_Xlo[3][GM_M * DD];
__device__ __nv_bfloat16 g_Wthi[3][DD * DD];
__device__ __nv_bfloat16 g_Wtlo[3][DD * DD];
// head-major attention operands
__device__ __nv_bfloat16 g_Qh[BB * HH * SS * DH];
__device__ __nv_bfloat16 g_Ql[BB * HH * SS * DH];
__device__ __nv_bfloat16 g_Kh[BB * HH * SS * DH];
__device__ __nv_bfloat16 g_Kl[BB * HH * SS * DH];
__device__ __nv_bfloat16 g_Vth[BB * HH * DH * SS];   // [bh][d][s]
__device__ __nv_bfloat16 g_Vtl[BB * HH * DH * SS];

// ---------------------------------------------------------------------------
// Helpers
// ---------------------------------------------------------------------------
__device__ __forceinline__ uint32_t smem_u32(const void* p) {
    uint32_t a;
    asm("{ .reg .u64 t; cvta.to.shared.u64 t, %1; cvt.u32.u64 %0, t; }" : "=r"(a) : "l"(p));
    return a;
}
#define LDSM_X4(r0, r1, r2, r3, addr) \
    asm volatile("ldmatrix.sync.aligned.m8n8.x4.shared.b16 {%0,%1,%2,%3}, [%4];" \
        : "=r"(r0), "=r"(r1), "=r"(r2), "=r"(r3) : "r"(addr))
#define MMA16816(d, a, b) \
    asm volatile("mma.sync.aligned.m16n8k16.row.col.f32.bf16.bf16.f32 " \
        "{%0,%1,%2,%3}, {%4,%5,%6,%7}, {%8,%9}, {%0,%1,%2,%3};" \
        : "+f"((d)[0]), "+f"((d)[1]), "+f"((d)[2]), "+f"((d)[3]) \
        : "r"((a)[0]), "r"((a)[1]), "r"((a)[2]), "r"((a)[3]), \
          "r"((b)[0]), "r"((b)[1]))
__device__ __forceinline__ void cp16(uint32_t saddr, const void* g) {
    asm volatile("cp.async.cg.shared.global [%0], [%1], 16;" :: "r"(saddr), "l"(g));
}
#define CP_COMMIT() asm volatile("cp.async.commit_group;" ::: "memory")
#define CP_WAIT(n)  asm volatile("cp.async.wait_group %0;" :: "n"(n) : "memory")

__device__ __forceinline__ uint32_t prmt(uint32_t a, uint32_t b, uint32_t sel) {
    uint32_t d;
    asm("prmt.b32 %0, %1, %2, %3;" : "=r"(d) : "r"(a), "r"(b), "r"(sel));
    return d;
}
__device__ __forceinline__ void splitf(float x, __nv_bfloat16& h, __nv_bfloat16& l) {
    h = __float2bfloat16(x);
    l = __float2bfloat16(x - __bfloat162float(h));
}
// pack two fp32 -> bf16x2 hi word + bf16x2 lo word
__device__ __forceinline__ void split2(float2 p, uint32_t& hi, uint32_t& lo) {
    __nv_bfloat16 hx, lx, hy, ly;
    splitf(p.x, hx, lx); splitf(p.y, hy, ly);
    __nv_bfloat162 h2 = __halves2bfloat162(hx, hy);
    __nv_bfloat162 l2 = __halves2bfloat162(lx, ly);
    hi = *reinterpret_cast<uint32_t*>(&h2);
    lo = *reinterpret_cast<uint32_t*>(&l2);
}

// ---------------------------------------------------------------------------
// Kernel: split fp32 -> bf16 hi/lo (q,k,v inputs); grid.y selects source
// ---------------------------------------------------------------------------
__global__ __launch_bounds__(256) void conv_split_kernel(
    const float4* __restrict__ q, const float4* __restrict__ k,
    const float4* __restrict__ v)
{
    int z = blockIdx.y;
    const float4* src = (z == 0) ? q : (z == 1) ? k : v;
    __nv_bfloat162* hi = reinterpret_cast<__nv_bfloat162*>(g_Xhi[z]);
    __nv_bfloat162* lo = reinterpret_cast<__nv_bfloat162*>(g_Xlo[z]);
    const int n4 = GM_M * DD / 4;
    for (int i = blockIdx.x * blockDim.x + threadIdx.x; i < n4; i += gridDim.x * blockDim.x) {
        float4 f = src[i];
        __nv_bfloat16 h0, l0, h1, l1, h2, l2, h3, l3;
        splitf(f.x, h0, l0); splitf(f.y, h1, l1);
        splitf(f.z, h2, l2); splitf(f.w, h3, l3);
        hi[2*i]   = __halves2bfloat162(h0, h1);
        hi[2*i+1] = __halves2bfloat162(h2, h3);
        lo[2*i]   = __halves2bfloat162(l0, l1);
        lo[2*i+1] = __halves2bfloat162(l2, l3);
    }
}

// ---------------------------------------------------------------------------
// Kernel: transpose + split W [k][n] -> Wt hi/lo [n][k]
// ---------------------------------------------------------------------------
__global__ __launch_bounds__(256) void conv_wt_kernel(
    const float* __restrict__ Wq, const float* __restrict__ Wk, const float* __restrict__ Wv)
{
    __shared__ float tile[32][33];
    int z = blockIdx.z;
    const float* W = (z == 0) ? Wq : (z == 1) ? Wk : Wv;
    __nv_bfloat16* Whi = g_Wthi[z];
    __nv_bfloat16* Wlo = g_Wtlo[z];

    int bx = blockIdx.x * 32;
    int by = blockIdx.y * 32;
    int tx = threadIdx.x;
    int ty = threadIdx.y;

    #pragma unroll
    for (int r = 0; r < 4; ++r) {
        int k = by + ty + r * 8;
        tile[ty + r * 8][tx] = W[(size_t)k * DD + bx + tx];
    }
    __syncthreads();
    #pragma unroll
    for (int r = 0; r < 4; ++r) {
        int n = bx + ty + r * 8;
        int k = by + tx;
        float v = tile[tx][ty + r * 8];
        __nv_bfloat16 h, l;
        splitf(v, h, l);
        Whi[(size_t)n * DD + k] = h;
        Wlo[(size_t)n * DD + k] = l;
    }
}

// ---------------------------------------------------------------------------
// Kernel: HMMA projection GEMM with fused head-major epilogue.
// z=0 -> Qh/Ql head-major bf16; z=1 -> Kh/Kl; z=2 -> fp32 g_V.
// CTA 128x128, BK=32, 8 warps (4Mx2N), 3-stage cp.async pipeline.
// ---------------------------------------------------------------------------
#define PROJ_STAGE_BYTES 40960
#define PROJ_SMEM_BYTES  (3 * PROJ_STAGE_BYTES)

__global__ __launch_bounds__(256) void proj_mma_kernel(
    const float* __restrict__ bq, const float* __restrict__ bk,
    const float* __restrict__ bv)
{
    extern __shared__ char smc[];
    const uint32_t smb = smem_u32(smc);
    const int tid  = threadIdx.x;
    const int lane = tid & 31;
    const int wid  = tid >> 5;
    const int wm   = wid & 3;
    const int wn   = wid >> 2;
    const int z  = blockIdx.z;
    const int n0 = blockIdx.x * 128;
    const int m0 = blockIdx.y * 128;

    const __nv_bfloat16* Xhi = g_Xhi[z];
    const __nv_bfloat16* Xlo = g_Xlo[z];
    const __nv_bfloat16* Whi = g_Wthi[z];
    const __nv_bfloat16* Wlo = g_Wtlo[z];
    const float* bias = (z == 0) ? bq : (z == 1) ? bk : bv;

    const int l_row[2] = { (tid + 0) >> 2, (tid + 256) >> 2 };
    const int l_seg[2] = { (tid + 0) & 3,  (tid + 256) & 3  };

    float acc[2][8][4];
    #pragma unroll
    for (int f = 0; f < 2; ++f)
        #pragma unroll
        for (int j = 0; j < 8; ++j)
            #pragma unroll
            for (int c = 0; c < 4; ++c) acc[f][j][c] = 0.0f;

    // ---- issue stages 0 and 1 ----
    #pragma unroll
    for (int st = 0; st < 2; ++st) {
        const int k0 = st * 32;
        uint32_t sb = smb + st * PROJ_STAGE_BYTES;
        #pragma unroll
        for (int t = 0; t < 2; ++t) {
            uint32_t so = (uint32_t)(l_row[t] * 80 + l_seg[t] * 16);
            size_t ga = (size_t)(m0 + l_row[t]) * DD + k0 + l_seg[t] * 8;
            size_t gb = (size_t)(n0 + l_row[t]) * DD + k0 + l_seg[t] * 8;
            cp16(sb +         so, Xhi + ga);
            cp16(sb + 10240 + so, Xlo + ga);
            cp16(sb + 20480 + so, Whi + gb);
            cp16(sb + 30720 + so, Wlo + gb);
        }
        CP_COMMIT();
    }

    const uint32_t a_off =
        (uint32_t)((wm * 32 + (lane & 15)) * 80 + (lane >> 4) * 16);
    const int bg = lane >> 3;
    const uint32_t b_off =
        (uint32_t)((wn * 64 + (bg >> 1) * 8 + (lane & 7)) * 80 + (bg & 1) * 16);

    int stage = 0;
    for (int i = 0; i < 32; ++i) {
        if (i < 30) {
            const int k0 = (i + 2) * 32;
            int st = (stage + 2) % 3;
            uint32_t sb = smb + st * PROJ_STAGE_BYTES;
            #pragma unroll
            for (int t = 0; t < 2; ++t) {
                uint32_t so = (uint32_t)(l_row[t] * 80 + l_seg[t] * 16);
                size_t ga = (size_t)(m0 + l_row[t]) * DD + k0 + l_seg[t] * 8;
                size_t gb = (size_t)(n0 + l_row[t]) * DD + k0 + l_seg[t] * 8;
                cp16(sb +         so, Xhi + ga);
                cp16(sb + 10240 + so, Xlo + ga);
                cp16(sb + 20480 + so, Whi + gb);
                cp16(sb + 30720 + so, Wlo + gb);
            }
            CP_COMMIT();
            CP_WAIT(2);
        } else if (i == 30) {
            CP_WAIT(1);
        } else {
            CP_WAIT(0);
        }
        __syncthreads();

        const uint32_t sb = smb + stage * PROJ_STAGE_BYTES;
        #pragma unroll
        for (int s = 0; s < 2; ++s) {
            const uint32_t ks = (uint32_t)(s * 32);
            uint32_t ah[2][4], al[2][4];
            #pragma unroll
            for (int f = 0; f < 2; ++f) {
                uint32_t aaddr = sb + a_off + (uint32_t)(f * 16 * 80) + ks;
                LDSM_X4(ah[f][0], ah[f][1], ah[f][2], ah[f][3], aaddr);
                LDSM_X4(al[f][0], al[f][1], al[f][2], al[f][3], aaddr + 10240);
            }
            uint32_t bh[4][4], bl[4][4];
            #pragma unroll
            for (int nf = 0; nf < 4; ++nf) {
                uint32_t baddr = sb + 20480 + b_off + (uint32_t)(nf * 16 * 80) + ks;
                LDSM_X4(bh[nf][0], bh[nf][1], bh[nf][2], bh[nf][3], baddr);
                LDSM_X4(bl[nf][0], bl[nf][1], bl[nf][2], bl[nf][3], baddr + 10240);
            }
            #pragma unroll
            for (int f = 0; f < 2; ++f) {
                #pragma unroll
                for (int j = 0; j < 8; ++j) {
                    uint32_t bfh[2] = { bh[j >> 1][(j & 1) * 2], bh[j >> 1][(j & 1) * 2 + 1] };
                    uint32_t bfl[2] = { bl[j >> 1][(j & 1) * 2], bl[j >> 1][(j & 1) * 2 + 1] };
                    MMA16816(acc[f][j], ah[f], bfh);
                    MMA16816(acc[f][j], ah[f], bfl);
                    MMA16816(acc[f][j], al[f], bfh);
                }
            }
        }
        __syncthreads();
        stage = (stage + 1) % 3;
    }

    // ---- epilogue ----
    const int er = m0 + wm * 32 + (lane >> 2);
    const int ec = n0 + wn * 64 + (lane & 3) * 2;
    if (z < 2) {
        __nv_bfloat16* Dh = z ? g_Kh : g_Qh;
        __nv_bfloat16* Dl = z ? g_Kl : g_Ql;
        #pragma unroll
        for (int f = 0; f < 2; ++f) {
            #pragma unroll
            for (int j = 0; j < 8; ++j) {
                int col = ec + j * 8;
                int hh = col >> 6, d = col & 63;
                float b0 = __ldg(bias + col);
                float b1 = __ldg(bias + col + 1);
                #pragma unroll
                for (int rr = 0; rr < 2; ++rr) {
                    int row = er + f * 16 + rr * 8;
                    int bb = row >> 10, s = row & 1023;
                    float v0 = acc[f][j][rr * 2 + 0] + b0;
                    float v1 = acc[f][j][rr * 2 + 1] + b1;
                    uint32_t hi, lo;
                    split2(make_float2(v0, v1), hi, lo);
                    size_t o = (((size_t)(bb * HH + hh)) * SS + s) * DH + d;
                    *(uint32_t*)(Dh + o) = hi;
                    *(uint32_t*)(Dl + o) = lo;
                }
            }
        }
    } else {
        #pragma unroll
        for (int f = 0; f < 2; ++f) {
            #pragma unroll
            for (int j = 0; j < 8; ++j) {
                int row = er + f * 16;
                int col = ec + j * 8;
                float b0 = __ldg(bias + col);
                float b1 = __ldg(bias + col + 1);
                float2 v0 = { acc[f][j][0] + b0, acc[f][j][1] + b1 };
                float2 v1 = { acc[f][j][2] + b0, acc[f][j][3] + b1 };
                *(float2*)(g_V + (size_t)row * DD + col)       = v0;
                *(float2*)(g_V + (size_t)(row + 8) * DD + col) = v1;
            }
        }
    }
}

// ---------------------------------------------------------------------------
// Kernel: V transpose + split: g_V -> Vt hi/lo [bh][d][s]
// ---------------------------------------------------------------------------
__global__ __launch_bounds__(256) void conv_vt_kernel()
{
    __shared__ float tile[64][33];
    int s0 = blockIdx.x * 32;
    int bh = blockIdx.y;
    int b = bh >> 4, h = bh & 15;
    int tid = threadIdx.x;

    #pragma unroll
    for (int t = 0; t < 2; ++t) {
        int i = tid + t * 256;
        int r = i >> 4, d4 = i & 15;
        float4 v = *(const float4*)(g_V + ((size_t)b * SS + s0 + r) * DD + h * 64 + d4 * 4);
        tile[d4 * 4 + 0][r] = v.x;
        tile[d4 * 4 + 1][r] = v.y;
        tile[d4 * 4 + 2][r] = v.z;
        tile[d4 * 4 + 3][r] = v.w;
    }
    __syncthreads();
    #pragma unroll
    for (int t = 0; t < 2; ++t) {
        int i = tid + t * 256;
        int d = i >> 3, sg = i & 7;
        size_t o = ((size_t)bh * DH + d) * SS + s0 + sg * 4;
        __nv_bfloat16 h0, l0, h1, l1, h2, l2, h3, l3;
        splitf(tile[d][sg * 4 + 0], h0, l0);
        splitf(tile[d][sg * 4 + 1], h1, l1);
        splitf(tile[d][sg * 4 + 2], h2, l2);
        splitf(tile[d][sg * 4 + 3], h3, l3);
        __nv_bfloat162* ph = (__nv_bfloat162*)(g_Vth + o);
        __nv_bfloat162* pl = (__nv_bfloat162*)(g_Vtl + o);
        ph[0] = __halves2bfloat162(h0, h1); ph[1] = __halves2bfloat162(h2, h3);
        pl[0] = __halves2bfloat162(l0, l1); pl[1] = __halves2bfloat162(l2, l3);
    }
}

// ---------------------------------------------------------------------------
// Kernel: attention with HMMA.  Softmax packs e as (bf16hi<<16)|bf16lo
// in-place in Ssc; PV unpacks with PRMT.
// ---------------------------------------------------------------------------
#define SSTR     1036
#define AT_QOFF  132608
#define AT_STG   141824
#define AT_BUF   36864
#define AT_INVS  215552
#define AT_SMEM  215680

__global__ __launch_bounds__(256) void attn_mma_kernel(
    float* __restrict__ ctx, float* __restrict__ attn)
{
    extern __shared__ char smc[];
    float* Ssc  = (float*)smc;
    float* invs = (float*)(smc + AT_INVS);
    const uint32_t smb = smem_u32(smc);
    const int tid = threadIdx.x, lane = tid & 31, wid = tid >> 5;
    const int q0 = blockIdx.x * 32;
    const int h  = blockIdx.y;
    const int b  = blockIdx.z;
    const int bh = b * HH + h;

    // ---- Q tile hi/lo into padded smem ----
    {
        int row = tid >> 3, seg = tid & 7;
        size_t g = ((size_t)bh * SS + q0 + row) * DH + seg * 8;
        *(uint4*)(smc + AT_QOFF + row * 144 + seg * 16)        = *(const uint4*)(g_Qh + g);
        *(uint4*)(smc + AT_QOFF + 4608 + row * 144 + seg * 16) = *(const uint4*)(g_Ql + g);
    }

    const __nv_bfloat16* Kh = g_Kh + (size_t)bh * SS * DH;
    const __nv_bfloat16* Kl = g_Kl + (size_t)bh * SS * DH;

    // ---- issue K chunk 0 ----
    {
        uint32_t sb = smb + AT_STG;
        #pragma unroll
        for (int t = 0; t < 4; ++t) {
            int idx = tid + t * 256;
            int row = idx >> 3, seg = idx & 7;
            uint32_t so = sb + row * 144 + seg * 16;
            cp16(so,         Kh + (size_t)row * DH + seg * 8);
            cp16(so + 18432, Kl + (size_t)row * DH + seg * 8);
        }
        CP_COMMIT();
    }

    // ---- scores ----
    const int wm = wid & 1, wn = wid >> 1;
    const int bg = lane >> 3;
    for (int ic = 0; ic < 8; ++ic) {
        if (ic < 7) {
            uint32_t sb = smb + AT_STG + ((ic + 1) & 1) * AT_BUF;
            const __nv_bfloat16* kh = Kh + (size_t)(ic + 1) * 128 * DH;
            const __nv_bfloat16* kl = Kl + (size_t)(ic + 1) * 128 * DH;
            #pragma unroll
            for (int t = 0; t < 4; ++t) {
                int idx = tid + t * 256;
                int row = idx >> 3, seg = idx & 7;
                uint32_t so = sb + row * 144 + seg * 16;
                cp16(so,         kh + (size_t)row * DH + seg * 8);
                cp16(so + 18432, kl + (size_t)row * DH + seg * 8);
            }
            CP_COMMIT();
            CP_WAIT(1);
        } else {
            CP_WAIT(0);
        }
        __syncthreads();

        uint32_t sb = smb + AT_STG + (ic & 1) * AT_BUF;
        float acc[4][4];
        #pragma unroll
        for (int jj = 0; jj < 4; ++jj)
            #pragma unroll
            for (int c = 0; c < 4; ++c) acc[jj][c] = 0.0f;

        #pragma unroll
        for (int ks = 0; ks < 4; ++ks) {
            uint32_t ah[4], al[4];
            uint32_t aaddr = smb + AT_QOFF + (wm * 16 + (lane & 15)) * 144
                           + (lane >> 4) * 16 + ks * 32;
            LDSM_X4(ah[0], ah[1], ah[2], ah[3], aaddr);
            LDSM_X4(al[0], al[1], al[2], al[3], aaddr + 4608);
            #pragma unroll
            for (int g = 0; g < 2; ++g) {
                uint32_t bhf[4], blf[4];
                uint32_t baddr = sb + (wn * 32 + g * 16 + (bg >> 1) * 8 + (lane & 7)) * 144
                               + (bg & 1) * 16 + ks * 32;
                LDSM_X4(bhf[0], bhf[1], bhf[2], bhf[3], baddr);
                LDSM_X4(blf[0], blf[1], blf[2], blf[3], baddr + 18432);
                #pragma unroll
                for (int j2 = 0; j2 < 2; ++j2) {
                    uint32_t b2h[2] = { bhf[j2 * 2], bhf[j2 * 2 + 1] };
                    uint32_t b2l[2] = { blf[j2 * 2], blf[j2 * 2 + 1] };
                    MMA16816(acc[g * 2 + j2], ah, b2h);
                    MMA16816(acc[g * 2 + j2], ah, b2l);
                    MMA16816(acc[g * 2 + j2], al, b2h);
                }
            }
        }
        int r = wm * 16 + (lane >> 2);
        #pragma unroll
        for (int jj = 0; jj < 4; ++jj) {
            int c = ic * 128 + wn * 32 + (jj >> 1) * 16 + (jj & 1) * 8 + (lane & 3) * 2;
            Ssc[r * SSTR + c]           = acc[jj][0] * 0.125f;
            Ssc[r * SSTR + c + 1]       = acc[jj][1] * 0.125f;
            Ssc[(r + 8) * SSTR + c]     = acc[jj][2] * 0.125f;
            Ssc[(r + 8) * SSTR + c + 1] = acc[jj][3] * 0.125f;
        }
        __syncthreads();
    }

    // ---- prefetch Vt chunk 0 (overlaps softmax) ----
    const __nv_bfloat16* Vh = g_Vth + (size_t)bh * DH * SS;
    const __nv_bfloat16* Vl = g_Vtl + (size_t)bh * DH * SS;
    {
        uint32_t sb = smb + AT_STG;
        #pragma unroll
        for (int t = 0; t < 4; ++t) {
            int idx = tid + t * 256;
            int row = idx >> 4, seg = idx & 15;
            uint32_t so = sb + row * 272 + seg * 16;
            cp16(so,         Vh + (size_t)row * SS + seg * 8);
            cp16(so + 17408, Vl + (size_t)row * SS + seg * 8);
        }
        CP_COMMIT();
    }

    // ---- softmax: warp handles its 4 rows sequentially, full-warp lanes ----
    #pragma unroll
    for (int rr = 0; rr < 4; ++rr) {
        const int row = wid * 4 + rr;
        float* srow = Ssc + row * SSTR;
        uint32_t* urow = (uint32_t*)srow;

        float m = -1e30f;
        #pragma unroll 4
        for (int t = lane; t < SS; t += 32) m = fmaxf(m, srow[t]);
        #pragma unroll
        for (int off = 16; off >= 1; off >>= 1)
            m = fmaxf(m, __shfl_xor_sync(0xffffffffu, m, off));

        float sum = 0.0f;
        #pragma unroll 4
        for (int t = lane; t < SS; t += 32) {
            float e = __expf(srow[t] - m);
            sum += e;
            __nv_bfloat16 hh = __float2bfloat16(e);
            __nv_bfloat16 ll = __float2bfloat16(e - __bfloat162float(hh));
            urow[t] = ((uint32_t)__bfloat16_as_ushort(hh) << 16) |
                      (uint32_t)__bfloat16_as_ushort(ll);
        }
        #pragma unroll
        for (int off = 16; off >= 1; off >>= 1)
            sum += __shfl_xor_sync(0xffffffffu, sum, off);
        float inv = 1.0f / sum;
        if (lane == 0) invs[row] = inv;

        float* arow = attn + ((size_t)(h * BB + b)) * SS * SS + (size_t)(q0 + row) * SS;
        #pragma unroll 4
        for (int t = lane; t < SS; t += 32) {
            uint32_t p = urow[t];
            float hv = __bfloat162float(__ushort_as_bfloat16((unsigned short)(p >> 16)));
            float lv = __bfloat162float(__ushort_as_bfloat16((unsigned short)(p & 0xffff)));
            arow[t] = (hv + lv) * inv;
        }
    }

    // ---- P @ V via HMMA (P already packed hi|lo in Ssc; PRMT unpack) ----
    const int wm2 = wid & 1, wn2 = wid >> 1;
    const uint32_t* Su = (const uint32_t*)Ssc;
    float acc2[2][4];
    #pragma unroll
    for (int j2 = 0; j2 < 2; ++j2)
        #pragma unroll
        for (int c = 0; c < 4; ++c) acc2[j2][c] = 0.0f;

    for (int jc = 0; jc < 8; ++jc) {
        if (jc < 7) {
            uint32_t sb = smb + AT_STG + ((jc + 1) & 1) * AT_BUF;
            const __nv_bfloat16* vh = Vh + (size_t)(jc + 1) * 128;
            const __nv_bfloat16* vl = Vl + (size_t)(jc + 1) * 128;
            #pragma unroll
            for (int t = 0; t < 4; ++t) {
                int idx = tid + t * 256;
                int row = idx >> 4, seg = idx & 15;
                uint32_t so = sb + row * 272 + seg * 16;
                cp16(so,         vh + (size_t)row * SS + seg * 8);
                cp16(so + 17408, vl + (size_t)row * SS + seg * 8);
            }
            CP_COMMIT();
            CP_WAIT(1);
        } else {
            CP_WAIT(0);
        }
        __syncthreads();

        uint32_t sb = smb + AT_STG + (jc & 1) * AT_BUF;
        const int ar = wm2 * 16 + (lane >> 2);
        #pragma unroll
        for (int ks = 0; ks < 8; ++ks) {
            int ac = jc * 128 + ks * 16 + (lane & 3) * 2;
            uint2 q00 = *(const uint2*)&Su[ar * SSTR + ac];
            uint2 q10 = *(const uint2*)&Su[(ar + 8) * SSTR + ac];
            uint2 q01 = *(const uint2*)&Su[ar * SSTR + ac + 8];
            uint2 q11 = *(const uint2*)&Su[(ar + 8) * SSTR + ac + 8];
            uint32_t ah[4], al[4];
            ah[0] = prmt(q00.x, q00.y, 0x7632); al[0] = prmt(q00.x, q00.y, 0x5410);
            ah[1] = prmt(q10.x, q10.y, 0x7632); al[1] = prmt(q10.x, q10.y, 0x5410);
            ah[2] = prmt(q01.x, q01.y, 0x7632); al[2] = prmt(q01.x, q01.y, 0x5410);
            ah[3] = prmt(q11.x, q11.y, 0x7632); al[3] = prmt(q11.x, q11.y, 0x5410);

            uint32_t bhf[4], blf[4];
            uint32_t baddr = sb + (wn2 * 16 + (bg >> 1) * 8 + (lane & 7)) * 272
                           + (bg & 1) * 16 + ks * 32;
            LDSM_X4(bhf[0], bhf[1], bhf[2], bhf[3], baddr);
            LDSM_X4(blf[0], blf[1], blf[2], blf[3], baddr + 17408);
            #pragma unroll
            for (int j2 = 0; j2 < 2; ++j2) {
                uint32_t b2h[2] = { bhf[j2 * 2], bhf[j2 * 2 + 1] };
                uint32_t b2l[2] = { blf[j2 * 2], blf[j2 * 2 + 1] };
                MMA16816(acc2[j2], ah, b2h);
                MMA16816(acc2[j2], ah, b2l);
                MMA16816(acc2[j2], al, b2h);
            }
        }
        __syncthreads();
    }

    // ---- context epilogue ----
    {
        int r = wm2 * 16 + (lane >> 2);
        float inv0 = invs[r];
        float inv1 = invs[r + 8];
        #pragma unroll
        for (int j2 = 0; j2 < 2; ++j2) {
            int c = h * 64 + wn2 * 16 + j2 * 8 + (lane & 3) * 2;
            float2 v0 = { acc2[j2][0] * inv0, acc2[j2][1] * inv0 };
            float2 v1 = { acc2[j2][2] * inv1, acc2[j2][3] * inv1 };
            *(float2*)&ctx[((size_t)b * SS + q0 + r) * DD + c]     = v0;
            *(float2*)&ctx[((size_t)b * SS + q0 + r + 8) * DD + c] = v1;
        }
    }
}

// ---------------------------------------------------------------------------
extern "C" void kernel_launch(void* const* d_in, const int* in_sizes, int n_in,
                              void* d_out, int out_size)
{
    const float* query = (const float*)d_in[0];
    const float* key   = (const float*)d_in[1];
    const float* value = (const float*)d_in[2];
    const float* Wq    = (const float*)d_in[3];
    const float* bq    = (const float*)d_in[4];
    const float* Wk    = (const float*)d_in[5];
    const float* bk    = (const float*)d_in[6];
    const float* Wv    = (const float*)d_in[7];
    const float* bv    = (const float*)d_in[8];

    float* out  = (float*)d_out;
    float* ctx  = out;
    float* attn = out + (size_t)BB * SS * DD;

    conv_split_kernel<<<dim3(512, 3), 256>>>(
        (const float4*)query, (const float4*)key, (const float4*)value);
    conv_wt_kernel<<<dim3(32, 32, 3), dim3(32, 8)>>>(Wq, Wk, Wv);

    cudaFuncSetAttribute(proj_mma_kernel, cudaFuncAttributeMaxDynamicSharedMemorySize,
                         PROJ_SMEM_BYTES);
    proj_mma_kernel<<<dim3(8, 32, 3), 256, PROJ_SMEM_BYTES>>>(bq, bk, bv);

    conv_vt_kernel<<<dim3(SS / 32, BB * HH), 256>>>();

    cudaFuncSetAttribute(attn_mma_kernel, cudaFuncAttributeMaxDynamicSharedMemorySize,
                         AT_SMEM);
    attn_mma_kernel<<<dim3(SS / 32, HH, BB), 256, AT_SMEM>>>(ctx, attn);
}

// round 6
// speedup vs baseline: 3.4265x; 1.0159x over previous
#include <cuda_runtime.h>
#include <cuda_bf16.h>
#include <cstdint>
#include <math.h>

// ---------------------------------------------------------------------------
// Problem constants
// ---------------------------------------------------------------------------
#define BB 4
#define SS 1024
#define DD 1024
#define HH 16
#define DH 64
#define GM_M (BB*SS)   // 4096

// ---------------------------------------------------------------------------
// Device scratch
// ---------------------------------------------------------------------------
__device__ float g_V[GM_M * DD];
__device__ __nv_bfloat16 g_Xhi[3][GM_M * DD];
__device__ __nv_bfloat16 g_Xlo[3][GM_M * DD];
__device__ __nv_bfloat16 g_Wthi[3][DD * DD];
__device__ __nv_bfloat16 g_Wtlo[3][DD * DD];
__device__ __nv_bfloat16 g_Qh[BB * HH * SS * DH];
__device__ __nv_bfloat16 g_Ql[BB * HH * SS * DH];
__device__ __nv_bfloat16 g_Kh[BB * HH * SS * DH];
__device__ __nv_bfloat16 g_Kl[BB * HH * SS * DH];
__device__ __nv_bfloat16 g_Vth[BB * HH * DH * SS];   // [bh][d][s]
__device__ __nv_bfloat16 g_Vtl[BB * HH * DH * SS];

// ---------------------------------------------------------------------------
// Helpers
// ---------------------------------------------------------------------------
__device__ __forceinline__ uint32_t smem_u32(const void* p) {
    uint32_t a;
    asm("{ .reg .u64 t; cvta.to.shared.u64 t, %1; cvt.u32.u64 %0, t; }" : "=r"(a) : "l"(p));
    return a;
}
#define LDSM_X4(r0, r1, r2, r3, addr) \
    asm volatile("ldmatrix.sync.aligned.m8n8.x4.shared.b16 {%0,%1,%2,%3}, [%4];" \
        : "=r"(r0), "=r"(r1), "=r"(r2), "=r"(r3) : "r"(addr))
#define MMA16816(d, a, b) \
    asm volatile("mma.sync.aligned.m16n8k16.row.col.f32.bf16.bf16.f32 " \
        "{%0,%1,%2,%3}, {%4,%5,%6,%7}, {%8,%9}, {%0,%1,%2,%3};" \
        : "+f"((d)[0]), "+f"((d)[1]), "+f"((d)[2]), "+f"((d)[3]) \
        : "r"((a)[0]), "r"((a)[1]), "r"((a)[2]), "r"((a)[3]), \
          "r"((b)[0]), "r"((b)[1]))
__device__ __forceinline__ void cp16(uint32_t saddr, const void* g) {
    asm volatile("cp.async.cg.shared.global [%0], [%1], 16;" :: "r"(saddr), "l"(g));
}
#define CP_COMMIT() asm volatile("cp.async.commit_group;" ::: "memory")
#define CP_WAIT(n)  asm volatile("cp.async.wait_group %0;" :: "n"(n) : "memory")

__device__ __forceinline__ uint32_t prmt(uint32_t a, uint32_t b, uint32_t sel) {
    uint32_t d;
    asm("prmt.b32 %0, %1, %2, %3;" : "=r"(d) : "r"(a), "r"(b), "r"(sel));
    return d;
}
__device__ __forceinline__ void splitf(float x, __nv_bfloat16& h, __nv_bfloat16& l) {
    h = __float2bfloat16(x);
    l = __float2bfloat16(x - __bfloat162float(h));
}
__device__ __forceinline__ void split2(float2 p, uint32_t& hi, uint32_t& lo) {
    __nv_bfloat16 hx, lx, hy, ly;
    splitf(p.x, hx, lx); splitf(p.y, hy, ly);
    __nv_bfloat162 h2 = __halves2bfloat162(hx, hy);
    __nv_bfloat162 l2 = __halves2bfloat162(lx, ly);
    hi = *reinterpret_cast<uint32_t*>(&h2);
    lo = *reinterpret_cast<uint32_t*>(&l2);
}

// ---------------------------------------------------------------------------
// Kernel: split fp32 -> bf16 hi/lo (q,k,v inputs); grid.y selects source
// ---------------------------------------------------------------------------
__global__ __launch_bounds__(256) void conv_split_kernel(
    const float4* __restrict__ q, const float4* __restrict__ k,
    const float4* __restrict__ v)
{
    int z = blockIdx.y;
    const float4* src = (z == 0) ? q : (z == 1) ? k : v;
    __nv_bfloat162* hi = reinterpret_cast<__nv_bfloat162*>(g_Xhi[z]);
    __nv_bfloat162* lo = reinterpret_cast<__nv_bfloat162*>(g_Xlo[z]);
    const int n4 = GM_M * DD / 4;
    for (int i = blockIdx.x * blockDim.x + threadIdx.x; i < n4; i += gridDim.x * blockDim.x) {
        float4 f = src[i];
        __nv_bfloat16 h0, l0, h1, l1, h2, l2, h3, l3;
        splitf(f.x, h0, l0); splitf(f.y, h1, l1);
        splitf(f.z, h2, l2); splitf(f.w, h3, l3);
        hi[2*i]   = __halves2bfloat162(h0, h1);
        hi[2*i+1] = __halves2bfloat162(h2, h3);
        lo[2*i]   = __halves2bfloat162(l0, l1);
        lo[2*i+1] = __halves2bfloat162(l2, l3);
    }
}

// ---------------------------------------------------------------------------
// Kernel: transpose + split W [k][n] -> Wt hi/lo [n][k]
// ---------------------------------------------------------------------------
__global__ __launch_bounds__(256) void conv_wt_kernel(
    const float* __restrict__ Wq, const float* __restrict__ Wk, const float* __restrict__ Wv)
{
    __shared__ float tile[32][33];
    int z = blockIdx.z;
    const float* W = (z == 0) ? Wq : (z == 1) ? Wk : Wv;
    __nv_bfloat16* Whi = g_Wthi[z];
    __nv_bfloat16* Wlo = g_Wtlo[z];

    int bx = blockIdx.x * 32;
    int by = blockIdx.y * 32;
    int tx = threadIdx.x;
    int ty = threadIdx.y;

    #pragma unroll
    for (int r = 0; r < 4; ++r) {
        int k = by + ty + r * 8;
        tile[ty + r * 8][tx] = W[(size_t)k * DD + bx + tx];
    }
    __syncthreads();
    #pragma unroll
    for (int r = 0; r < 4; ++r) {
        int n = bx + ty + r * 8;
        int k = by + tx;
        float v = tile[tx][ty + r * 8];
        __nv_bfloat16 h, l;
        splitf(v, h, l);
        Whi[(size_t)n * DD + k] = h;
        Wlo[(size_t)n * DD + k] = l;
    }
}

// ---------------------------------------------------------------------------
// Kernel: HMMA projection GEMM, 512 threads / 16 warps (4M x 4N), warp 32x32.
// z=0 -> Qh/Ql head-major; z=1 -> Kh/Kl; z=2 -> fp32 g_V. 2-stage cp.async.
// ---------------------------------------------------------------------------
#define PROJ_STAGE_BYTES 40960
#define PROJ_SMEM_BYTES  (2 * PROJ_STAGE_BYTES)

__global__ __launch_bounds__(512) void proj_mma_kernel(
    const float* __restrict__ bq, const float* __restrict__ bk,
    const float* __restrict__ bv)
{
    extern __shared__ char smc[];
    const uint32_t smb = smem_u32(smc);
    const int tid  = threadIdx.x;
    const int lane = tid & 31;
    const int wid  = tid >> 5;       // 0..15
    const int wm   = wid & 3;        // M quadrant
    const int wn   = wid >> 2;       // N quadrant
    const int z  = blockIdx.z;
    const int n0 = blockIdx.x * 128;
    const int m0 = blockIdx.y * 128;

    const __nv_bfloat16* Xhi = g_Xhi[z];
    const __nv_bfloat16* Xlo = g_Xlo[z];
    const __nv_bfloat16* Whi = g_Wthi[z];
    const __nv_bfloat16* Wlo = g_Wtlo[z];
    const float* bias = (z == 0) ? bq : (z == 1) ? bk : bv;

    const int l_row = tid >> 2;      // 0..127
    const int l_seg = tid & 3;       // 0..3 (16B segs in 64B row)

    float acc[2][4][4];
    #pragma unroll
    for (int f = 0; f < 2; ++f)
        #pragma unroll
        for (int j = 0; j < 4; ++j)
            #pragma unroll
            for (int c = 0; c < 4; ++c) acc[f][j][c] = 0.0f;

    // ---- issue stage 0 ----
    {
        uint32_t sb = smb;
        uint32_t so = (uint32_t)(l_row * 80 + l_seg * 16);
        size_t ga = (size_t)(m0 + l_row) * DD + l_seg * 8;
        size_t gb = (size_t)(n0 + l_row) * DD + l_seg * 8;
        cp16(sb +         so, Xhi + ga);
        cp16(sb + 10240 + so, Xlo + ga);
        cp16(sb + 20480 + so, Whi + gb);
        cp16(sb + 30720 + so, Wlo + gb);
        CP_COMMIT();
    }

    const uint32_t a_off =
        (uint32_t)((wm * 32 + (lane & 15)) * 80 + (lane >> 4) * 16);
    const int bg = lane >> 3;
    const uint32_t b_off =
        (uint32_t)((wn * 32 + (bg >> 1) * 8 + (lane & 7)) * 80 + (bg & 1) * 16);

    for (int i = 0; i < 32; ++i) {
        if (i < 31) {
            const int k0 = (i + 1) * 32;
            uint32_t sb = smb + ((i + 1) & 1) * PROJ_STAGE_BYTES;
            uint32_t so = (uint32_t)(l_row * 80 + l_seg * 16);
            size_t ga = (size_t)(m0 + l_row) * DD + k0 + l_seg * 8;
            size_t gb = (size_t)(n0 + l_row) * DD + k0 + l_seg * 8;
            cp16(sb +         so, Xhi + ga);
            cp16(sb + 10240 + so, Xlo + ga);
            cp16(sb + 20480 + so, Whi + gb);
            cp16(sb + 30720 + so, Wlo + gb);
            CP_COMMIT();
            CP_WAIT(1);
        } else {
            CP_WAIT(0);
        }
        __syncthreads();

        const uint32_t sb = smb + (i & 1) * PROJ_STAGE_BYTES;
        #pragma unroll
        for (int s = 0; s < 2; ++s) {
            const uint32_t ks = (uint32_t)(s * 32);
            uint32_t ah[2][4], al[2][4];
            #pragma unroll
            for (int f = 0; f < 2; ++f) {
                uint32_t aaddr = sb + a_off + (uint32_t)(f * 16 * 80) + ks;
                LDSM_X4(ah[f][0], ah[f][1], ah[f][2], ah[f][3], aaddr);
                LDSM_X4(al[f][0], al[f][1], al[f][2], al[f][3], aaddr + 10240);
            }
            uint32_t bh[2][4], bl[2][4];
            #pragma unroll
            for (int nf = 0; nf < 2; ++nf) {
                uint32_t baddr = sb + 20480 + b_off + (uint32_t)(nf * 16 * 80) + ks;
                LDSM_X4(bh[nf][0], bh[nf][1], bh[nf][2], bh[nf][3], baddr);
                LDSM_X4(bl[nf][0], bl[nf][1], bl[nf][2], bl[nf][3], baddr + 10240);
            }
            #pragma unroll
            for (int f = 0; f < 2; ++f) {
                #pragma unroll
                for (int j = 0; j < 4; ++j) {
                    uint32_t bfh[2] = { bh[j >> 1][(j & 1) * 2], bh[j >> 1][(j & 1) * 2 + 1] };
                    uint32_t bfl[2] = { bl[j >> 1][(j & 1) * 2], bl[j >> 1][(j & 1) * 2 + 1] };
                    MMA16816(acc[f][j], ah[f], bfh);
                    MMA16816(acc[f][j], ah[f], bfl);
                    MMA16816(acc[f][j], al[f], bfh);
                }
            }
        }
        __syncthreads();
    }

    // ---- epilogue ----
    const int er = m0 + wm * 32 + (lane >> 2);
    const int ec = n0 + wn * 32 + (lane & 3) * 2;
    if (z < 2) {
        __nv_bfloat16* Dh = z ? g_Kh : g_Qh;
        __nv_bfloat16* Dl = z ? g_Kl : g_Ql;
        #pragma unroll
        for (int f = 0; f < 2; ++f) {
            #pragma unroll
            for (int j = 0; j < 4; ++j) {
                int col = ec + j * 8;
                int hh = col >> 6, d = col & 63;
                float b0 = __ldg(bias + col);
                float b1 = __ldg(bias + col + 1);
                #pragma unroll
                for (int rr = 0; rr < 2; ++rr) {
                    int row = er + f * 16 + rr * 8;
                    int bb = row >> 10, s = row & 1023;
                    float v0 = acc[f][j][rr * 2 + 0] + b0;
                    float v1 = acc[f][j][rr * 2 + 1] + b1;
                    uint32_t hi, lo;
                    split2(make_float2(v0, v1), hi, lo);
                    size_t o = (((size_t)(bb * HH + hh)) * SS + s) * DH + d;
                    *(uint32_t*)(Dh + o) = hi;
                    *(uint32_t*)(Dl + o) = lo;
                }
            }
        }
    } else {
        #pragma unroll
        for (int f = 0; f < 2; ++f) {
            #pragma unroll
            for (int j = 0; j < 4; ++j) {
                int row = er + f * 16;
                int col = ec + j * 8;
                float b0 = __ldg(bias + col);
                float b1 = __ldg(bias + col + 1);
                float2 v0 = { acc[f][j][0] + b0, acc[f][j][1] + b1 };
                float2 v1 = { acc[f][j][2] + b0, acc[f][j][3] + b1 };
                *(float2*)(g_V + (size_t)row * DD + col)       = v0;
                *(float2*)(g_V + (size_t)(row + 8) * DD + col) = v1;
            }
        }
    }
}

// ---------------------------------------------------------------------------
// Kernel: V transpose + split: g_V -> Vt hi/lo [bh][d][s]
// ---------------------------------------------------------------------------
__global__ __launch_bounds__(256) void conv_vt_kernel()
{
    __shared__ float tile[64][33];
    int s0 = blockIdx.x * 32;
    int bh = blockIdx.y;
    int b = bh >> 4, h = bh & 15;
    int tid = threadIdx.x;

    #pragma unroll
    for (int t = 0; t < 2; ++t) {
        int i = tid + t * 256;
        int r = i >> 4, d4 = i & 15;
        float4 v = *(const float4*)(g_V + ((size_t)b * SS + s0 + r) * DD + h * 64 + d4 * 4);
        tile[d4 * 4 + 0][r] = v.x;
        tile[d4 * 4 + 1][r] = v.y;
        tile[d4 * 4 + 2][r] = v.z;
        tile[d4 * 4 + 3][r] = v.w;
    }
    __syncthreads();
    #pragma unroll
    for (int t = 0; t < 2; ++t) {
        int i = tid + t * 256;
        int d = i >> 3, sg = i & 7;
        size_t o = ((size_t)bh * DH + d) * SS + s0 + sg * 4;
        __nv_bfloat16 h0, l0, h1, l1, h2, l2, h3, l3;
        splitf(tile[d][sg * 4 + 0], h0, l0);
        splitf(tile[d][sg * 4 + 1], h1, l1);
        splitf(tile[d][sg * 4 + 2], h2, l2);
        splitf(tile[d][sg * 4 + 3], h3, l3);
        __nv_bfloat162* ph = (__nv_bfloat162*)(g_Vth + o);
        __nv_bfloat162* pl = (__nv_bfloat162*)(g_Vtl + o);
        ph[0] = __halves2bfloat162(h0, h1); ph[1] = __halves2bfloat162(h2, h3);
        pl[0] = __halves2bfloat162(l0, l1); pl[1] = __halves2bfloat162(l2, l3);
    }
}

// ---------------------------------------------------------------------------
// Kernel: attention with HMMA, 512 threads / 16 warps.
// QK: warp tile 16x16 (2M x 8N).  PV: warp-halves alternate chunks,
// partials merged via smem.
// ---------------------------------------------------------------------------
#define SSTR     1036
#define AT_QOFF  132608
#define AT_STG   141824
#define AT_BUF   36864
#define AT_INVS  215552
#define AT_SMEM  215680

__global__ __launch_bounds__(512) void attn_mma_kernel(
    float* __restrict__ ctx, float* __restrict__ attn)
{
    extern __shared__ char smc[];
    float* Ssc  = (float*)smc;
    float* invs = (float*)(smc + AT_INVS);
    const uint32_t smb = smem_u32(smc);
    const int tid = threadIdx.x, lane = tid & 31, wid = tid >> 5;  // wid 0..15
    const int q0 = blockIdx.x * 32;
    const int h  = blockIdx.y;
    const int b  = blockIdx.z;
    const int bh = b * HH + h;

    // ---- Q tile hi/lo into padded smem ----
    if (tid < 256) {
        int row = tid >> 3, seg = tid & 7;
        size_t g = ((size_t)bh * SS + q0 + row) * DH + seg * 8;
        *(uint4*)(smc + AT_QOFF + row * 144 + seg * 16)        = *(const uint4*)(g_Qh + g);
        *(uint4*)(smc + AT_QOFF + 4608 + row * 144 + seg * 16) = *(const uint4*)(g_Ql + g);
    }

    const __nv_bfloat16* Kh = g_Kh + (size_t)bh * SS * DH;
    const __nv_bfloat16* Kl = g_Kl + (size_t)bh * SS * DH;

    // ---- issue K chunk 0 ----
    {
        uint32_t sb = smb + AT_STG;
        #pragma unroll
        for (int t = 0; t < 2; ++t) {
            int idx = tid + t * 512;
            int row = idx >> 3, seg = idx & 7;
            uint32_t so = sb + row * 144 + seg * 16;
            cp16(so,         Kh + (size_t)row * DH + seg * 8);
            cp16(so + 18432, Kl + (size_t)row * DH + seg * 8);
        }
        CP_COMMIT();
    }

    // ---- scores: warp (wm, wn) -> rows wm*16+16, cols wn*16 per 128-chunk ----
    const int wm = wid & 1, wn = wid >> 1;    // wn 0..7
    const int bg = lane >> 3;
    for (int ic = 0; ic < 8; ++ic) {
        if (ic < 7) {
            uint32_t sb = smb + AT_STG + ((ic + 1) & 1) * AT_BUF;
            const __nv_bfloat16* kh = Kh + (size_t)(ic + 1) * 128 * DH;
            const __nv_bfloat16* kl = Kl + (size_t)(ic + 1) * 128 * DH;
            #pragma unroll
            for (int t = 0; t < 2; ++t) {
                int idx = tid + t * 512;
                int row = idx >> 3, seg = idx & 7;
                uint32_t so = sb + row * 144 + seg * 16;
                cp16(so,         kh + (size_t)row * DH + seg * 8);
                cp16(so + 18432, kl + (size_t)row * DH + seg * 8);
            }
            CP_COMMIT();
            CP_WAIT(1);
        } else {
            CP_WAIT(0);
        }
        __syncthreads();

        uint32_t sb = smb + AT_STG + (ic & 1) * AT_BUF;
        float acc[2][4];
        #pragma unroll
        for (int j2 = 0; j2 < 2; ++j2)
            #pragma unroll
            for (int c = 0; c < 4; ++c) acc[j2][c] = 0.0f;

        #pragma unroll
        for (int ks = 0; ks < 4; ++ks) {
            uint32_t ah[4], al[4];
            uint32_t aaddr = smb + AT_QOFF + (wm * 16 + (lane & 15)) * 144
                           + (lane >> 4) * 16 + ks * 32;
            LDSM_X4(ah[0], ah[1], ah[2], ah[3], aaddr);
            LDSM_X4(al[0], al[1], al[2], al[3], aaddr + 4608);
            uint32_t bhf[4], blf[4];
            uint32_t baddr = sb + (wn * 16 + (bg >> 1) * 8 + (lane & 7)) * 144
                           + (bg & 1) * 16 + ks * 32;
            LDSM_X4(bhf[0], bhf[1], bhf[2], bhf[3], baddr);
            LDSM_X4(blf[0], blf[1], blf[2], blf[3], baddr + 18432);
            #pragma unroll
            for (int j2 = 0; j2 < 2; ++j2) {
                uint32_t b2h[2] = { bhf[j2 * 2], bhf[j2 * 2 + 1] };
                uint32_t b2l[2] = { blf[j2 * 2], blf[j2 * 2 + 1] };
                MMA16816(acc[j2], ah, b2h);
                MMA16816(acc[j2], ah, b2l);
                MMA16816(acc[j2], al, b2h);
            }
        }
        int r = wm * 16 + (lane >> 2);
        #pragma unroll
        for (int j2 = 0; j2 < 2; ++j2) {
            int c = ic * 128 + wn * 16 + j2 * 8 + (lane & 3) * 2;
            Ssc[r * SSTR + c]           = acc[j2][0] * 0.125f;
            Ssc[r * SSTR + c + 1]       = acc[j2][1] * 0.125f;
            Ssc[(r + 8) * SSTR + c]     = acc[j2][2] * 0.125f;
            Ssc[(r + 8) * SSTR + c + 1] = acc[j2][3] * 0.125f;
        }
        __syncthreads();
    }

    // ---- prefetch Vt chunk 0 (overlaps softmax) ----
    const __nv_bfloat16* Vh = g_Vth + (size_t)bh * DH * SS;
    const __nv_bfloat16* Vl = g_Vtl + (size_t)bh * DH * SS;
    {
        uint32_t sb = smb + AT_STG;
        #pragma unroll
        for (int t = 0; t < 2; ++t) {
            int idx = tid + t * 512;
            int row = idx >> 4, seg = idx & 15;
            uint32_t so = sb + row * 272 + seg * 16;
            cp16(so,         Vh + (size_t)row * SS + seg * 8);
            cp16(so + 17408, Vl + (size_t)row * SS + seg * 8);
        }
        CP_COMMIT();
    }

    // ---- softmax: 16 warps x 2 rows ----
    #pragma unroll
    for (int rr = 0; rr < 2; ++rr) {
        const int row = wid * 2 + rr;
        float* srow = Ssc + row * SSTR;
        uint32_t* urow = (uint32_t*)srow;

        float m = -1e30f;
        #pragma unroll 4
        for (int t = lane; t < SS; t += 32) m = fmaxf(m, srow[t]);
        #pragma unroll
        for (int off = 16; off >= 1; off >>= 1)
            m = fmaxf(m, __shfl_xor_sync(0xffffffffu, m, off));

        float sum = 0.0f;
        #pragma unroll 4
        for (int t = lane; t < SS; t += 32) {
            float e = __expf(srow[t] - m);
            sum += e;
            __nv_bfloat16 hh = __float2bfloat16(e);
            __nv_bfloat16 ll = __float2bfloat16(e - __bfloat162float(hh));
            urow[t] = ((uint32_t)__bfloat16_as_ushort(hh) << 16) |
                      (uint32_t)__bfloat16_as_ushort(ll);
        }
        #pragma unroll
        for (int off = 16; off >= 1; off >>= 1)
            sum += __shfl_xor_sync(0xffffffffu, sum, off);
        float inv = 1.0f / sum;
        if (lane == 0) invs[row] = inv;

        float* arow = attn + ((size_t)(h * BB + b)) * SS * SS + (size_t)(q0 + row) * SS;
        #pragma unroll 4
        for (int t = lane; t < SS; t += 32) {
            uint32_t p = urow[t];
            float hv = __bfloat162float(__ushort_as_bfloat16((unsigned short)(p >> 16)));
            float lv = __bfloat162float(__ushort_as_bfloat16((unsigned short)(p & 0xffff)));
            arow[t] = (hv + lv) * inv;
        }
    }

    // ---- P @ V: warp-halves alternate chunks; partials merged at the end ----
    const int grp = wid >> 3;                 // 0 or 1
    const int wm2 = wid & 1, wn2 = (wid >> 1) & 3;
    const uint32_t* Su = (const uint32_t*)Ssc;
    float acc2[2][4];
    #pragma unroll
    for (int j2 = 0; j2 < 2; ++j2)
        #pragma unroll
        for (int c = 0; c < 4; ++c) acc2[j2][c] = 0.0f;

    for (int jc = 0; jc < 8; ++jc) {
        if (jc < 7) {
            uint32_t sb = smb + AT_STG + ((jc + 1) & 1) * AT_BUF;
            const __nv_bfloat16* vh = Vh + (size_t)(jc + 1) * 128;
            const __nv_bfloat16* vl = Vl + (size_t)(jc + 1) * 128;
            #pragma unroll
            for (int t = 0; t < 2; ++t) {
                int idx = tid + t * 512;
                int row = idx >> 4, seg = idx & 15;
                uint32_t so = sb + row * 272 + seg * 16;
                cp16(so,         vh + (size_t)row * SS + seg * 8);
                cp16(so + 17408, vl + (size_t)row * SS + seg * 8);
            }
            CP_COMMIT();
            CP_WAIT(1);
        } else {
            CP_WAIT(0);
        }
        __syncthreads();

        if ((jc & 1) == grp) {
            uint32_t sb = smb + AT_STG + (jc & 1) * AT_BUF;
            const int ar = wm2 * 16 + (lane >> 2);
            #pragma unroll
            for (int ks = 0; ks < 8; ++ks) {
                int ac = jc * 128 + ks * 16 + (lane & 3) * 2;
                uint2 q00 = *(const uint2*)&Su[ar * SSTR + ac];
                uint2 q10 = *(const uint2*)&Su[(ar + 8) * SSTR + ac];
                uint2 q01 = *(const uint2*)&Su[ar * SSTR + ac + 8];
                uint2 q11 = *(const uint2*)&Su[(ar + 8) * SSTR + ac + 8];
                uint32_t ah[4], al[4];
                ah[0] = prmt(q00.x, q00.y, 0x7632); al[0] = prmt(q00.x, q00.y, 0x5410);
                ah[1] = prmt(q10.x, q10.y, 0x7632); al[1] = prmt(q10.x, q10.y, 0x5410);
                ah[2] = prmt(q01.x, q01.y, 0x7632); al[2] = prmt(q01.x, q01.y, 0x5410);
                ah[3] = prmt(q11.x, q11.y, 0x7632); al[3] = prmt(q11.x, q11.y, 0x5410);

                uint32_t bhf[4], blf[4];
                uint32_t baddr = sb + (wn2 * 16 + (bg >> 1) * 8 + (lane & 7)) * 272
                               + (bg & 1) * 16 + ks * 32;
                LDSM_X4(bhf[0], bhf[1], bhf[2], bhf[3], baddr);
                LDSM_X4(blf[0], blf[1], blf[2], blf[3], baddr + 17408);
                #pragma unroll
                for (int j2 = 0; j2 < 2; ++j2) {
                    uint32_t b2h[2] = { bhf[j2 * 2], bhf[j2 * 2 + 1] };
                    uint32_t b2l[2] = { blf[j2 * 2], blf[j2 * 2 + 1] };
                    MMA16816(acc2[j2], ah, b2h);
                    MMA16816(acc2[j2], ah, b2l);
                    MMA16816(acc2[j2], al, b2h);
                }
            }
        }
        __syncthreads();
    }

    // ---- merge warp-half partials and write context ----
    float* red = Ssc;   // reuse score smem
    if (grp == 1) {
        #pragma unroll
        for (int j2 = 0; j2 < 2; ++j2)
            #pragma unroll
            for (int c = 0; c < 4; ++c)
                red[(((wid - 8) * 2 + j2) * 4 + c) * 32 + lane] = acc2[j2][c];
    }
    __syncthreads();
    if (grp == 0) {
        int r = wm2 * 16 + (lane >> 2);
        float inv0 = invs[r];
        float inv1 = invs[r + 8];
        #pragma unroll
        for (int j2 = 0; j2 < 2; ++j2) {
            float p0 = red[((wid * 2 + j2) * 4 + 0) * 32 + lane];
            float p1 = red[((wid * 2 + j2) * 4 + 1) * 32 + lane];
            float p2 = red[((wid * 2 + j2) * 4 + 2) * 32 + lane];
            float p3 = red[((wid * 2 + j2) * 4 + 3) * 32 + lane];
            int c = h * 64 + wn2 * 16 + j2 * 8 + (lane & 3) * 2;
            float2 v0 = { (acc2[j2][0] + p0) * inv0, (acc2[j2][1] + p1) * inv0 };
            float2 v1 = { (acc2[j2][2] + p2) * inv1, (acc2[j2][3] + p3) * inv1 };
            *(float2*)&ctx[((size_t)b * SS + q0 + r) * DD + c]     = v0;
            *(float2*)&ctx[((size_t)b * SS + q0 + r + 8) * DD + c] = v1;
        }
    }
}

// ---------------------------------------------------------------------------
extern "C" void kernel_launch(void* const* d_in, const int* in_sizes, int n_in,
                              void* d_out, int out_size)
{
    const float* query = (const float*)d_in[0];
    const float* key   = (const float*)d_in[1];
    const float* value = (const float*)d_in[2];
    const float* Wq    = (const float*)d_in[3];
    const float* bq    = (const float*)d_in[4];
    const float* Wk    = (const float*)d_in[5];
    const float* bk    = (const float*)d_in[6];
    const float* Wv    = (const float*)d_in[7];
    const float* bv    = (const float*)d_in[8];

    float* out  = (float*)d_out;
    float* ctx  = out;
    float* attn = out + (size_t)BB * SS * DD;

    conv_split_kernel<<<dim3(512, 3), 256>>>(
        (const float4*)query, (const float4*)key, (const float4*)value);
    conv_wt_kernel<<<dim3(32, 32, 3), dim3(32, 8)>>>(Wq, Wk, Wv);

    cudaFuncSetAttribute(proj_mma_kernel, cudaFuncAttributeMaxDynamicSharedMemorySize,
                         PROJ_SMEM_BYTES);
    proj_mma_kernel<<<dim3(8, 32, 3), 512, PROJ_SMEM_BYTES>>>(bq, bk, bv);

    conv_vt_kernel<<<dim3(SS / 32, BB * HH), 256>>>();

    cudaFuncSetAttribute(attn_mma_kernel, cudaFuncAttributeMaxDynamicSharedMemorySize,
                         AT_SMEM);
    attn_mma_kernel<<<dim3(SS / 32, HH, BB), 512, AT_SMEM>>>(ctx, attn);
}